// round 9
// baseline (speedup 1.0000x reference)
#include <cuda_runtime.h>
#include <math.h>

// ---------------- problem constants ----------------
#define Bc   4
#define Sc   4096
#define Dc   256
#define Hc   4
#define DHc  64
#define Mc   266
#define Lc   4
#define NROWS (Bc*Sc)   // 16384
#define FFc  (4*Dc)     // 1024
#define BHc  (Bc*Hc)    // 16

#define DN_CONST    0.3535533905932738f     // 64^-0.25
#define DIAG_SCALE  0.0625f                 // 0.5*dn^2
#define RATIO_CONST 0.06131393394849658f    // 266^-0.5
#define PHI_EPS     1e-4f
#define LN_EPS      1e-12f

// ---------------- scratch (device globals; no allocs) ----------------
__device__ float g_x   [NROWS*Dc];
__device__ float g_xn  [NROWS*Dc];
__device__ float g_q   [NROWS*Dc];
__device__ float g_k   [NROWS*Dc];
__device__ float g_v   [NROWS*Dc];
__device__ float g_attn[NROWS*Dc];
__device__ float g_hid [NROWS*FFc];
__device__ float g_qp  [BHc*Sc*Mc];
__device__ float g_kp  [BHc*Sc*Mc];
__device__ float g_diag[BHc*Sc];
__device__ float g_dinv[BHc*Sc];
__device__ float g_ctx [BHc*Mc*DHc];
__device__ float g_ksum[BHc*Mc];
__device__ float g_ctxp [8*BHc*Mc*DHc];
__device__ float g_ksump[8*BHc*Mc];
__device__ float g_alpha[NROWS];
__device__ float g_asum [Bc];
__device__ float g_poolp[32*Bc*Dc];
__device__ float g_kmax;

// ---------------- helpers ----------------
__device__ __forceinline__ void atomicMaxFloat(float* addr, float val){
    if (val >= 0.f) atomicMax((int*)addr, __float_as_int(val));
    else            atomicMin((unsigned int*)addr, __float_as_uint(val));
}

// ---------------- LayerNorm kernels (one block per row, 256 threads) ----------------
__global__ __launch_bounds__(256)
void ln_embed_kernel(const float* __restrict__ emb, const float* __restrict__ pos,
                     const float* __restrict__ gam, const float* __restrict__ bet,
                     float* __restrict__ out){
    int row = blockIdx.x;
    int t   = threadIdx.x;
    float v = emb[row*Dc + t] + pos[(row & (Sc-1))*Dc + t];
    float s1 = v, s2 = v*v;
    __shared__ float sa[8], sb[8];
    #pragma unroll
    for (int o=16;o;o>>=1){ s1 += __shfl_xor_sync(0xffffffffu,s1,o); s2 += __shfl_xor_sync(0xffffffffu,s2,o); }
    if ((t&31)==0){ sa[t>>5]=s1; sb[t>>5]=s2; }
    __syncthreads();
    if (t==0){ float a=0,b=0; for(int i=0;i<8;i++){a+=sa[i]; b+=sb[i];} sa[0]=a; sb[0]=b; }
    __syncthreads();
    float mu  = sa[0]*(1.f/Dc);
    float var = sb[0]*(1.f/Dc) - mu*mu;
    out[row*Dc + t] = (v-mu)*rsqrtf(var+LN_EPS)*gam[t] + bet[t];
}

__global__ __launch_bounds__(256)
void ln_kernel(const float* __restrict__ in,
               const float* __restrict__ gam, const float* __restrict__ bet,
               float* __restrict__ out){
    int row = blockIdx.x;
    int t   = threadIdx.x;
    float v = in[row*Dc + t];
    float s1 = v, s2 = v*v;
    __shared__ float sa[8], sb[8];
    #pragma unroll
    for (int o=16;o;o>>=1){ s1 += __shfl_xor_sync(0xffffffffu,s1,o); s2 += __shfl_xor_sync(0xffffffffu,s2,o); }
    if ((t&31)==0){ sa[t>>5]=s1; sb[t>>5]=s2; }
    __syncthreads();
    if (t==0){ float a=0,b=0; for(int i=0;i<8;i++){a+=sa[i]; b+=sb[i];} sa[0]=a; sb[0]=b; }
    __syncthreads();
    float mu  = sa[0]*(1.f/Dc);
    float var = sb[0]*(1.f/Dc) - mu*mu;
    out[row*Dc + t] = (v-mu)*rsqrtf(var+LN_EPS)*gam[t] + bet[t];
}

// ---------------- SGEMM 128x128x8, 8x8 microtile: C = act(A@W + bias [+ res]) ----------------
// A[R,K] row-major, W[K,N] row-major. 256 threads. K%8==0, N%128==0, R%128==0.
__global__ __launch_bounds__(256)
void gemm_kernel(const float* __restrict__ A, const float* __restrict__ W,
                 const float* __restrict__ bias, const float* __restrict__ res,
                 float* __restrict__ C, int K, int N, int act){
    __shared__ float As[8][132];
    __shared__ float Bs[8][128];
    int bm = blockIdx.y * 128;
    int bn = blockIdx.x * 128;
    int tid = threadIdx.x;
    int tr = tid >> 4;         // 0..15
    int tc = tid & 15;         // 0..15
    // A loader: 128 rows x 8 k, float4 along k
    int lar = tid >> 1, lak = (tid & 1) * 4;
    // B loader: 8 rows x 128 cols, float4 along cols
    int lbk = tid >> 5, lbc = (tid & 31) * 4;
    const float* Aptr = A + (bm + lar)*K + lak;
    const float* Wptr = W + lbk*N + bn + lbc;
    float acc[8][8] = {};
    for (int k0 = 0; k0 < K; k0 += 8){
        float4 a4 = *(const float4*)(Aptr + k0);
        As[lak+0][lar] = a4.x; As[lak+1][lar] = a4.y;
        As[lak+2][lar] = a4.z; As[lak+3][lar] = a4.w;
        *(float4*)(&Bs[lbk][lbc]) = *(const float4*)(Wptr + k0*N);
        __syncthreads();
        #pragma unroll
        for (int k = 0; k < 8; k++){
            float a[8], b[8];
            *(float4*)(a)   = *(const float4*)(&As[k][tr*4]);
            *(float4*)(a+4) = *(const float4*)(&As[k][64 + tr*4]);
            *(float4*)(b)   = *(const float4*)(&Bs[k][tc*4]);
            *(float4*)(b+4) = *(const float4*)(&Bs[k][64 + tc*4]);
            #pragma unroll
            for (int i = 0; i < 8; i++)
                #pragma unroll
                for (int j = 0; j < 8; j++)
                    acc[i][j] += a[i]*b[j];
        }
        __syncthreads();
    }
    #pragma unroll
    for (int ih = 0; ih < 2; ih++){
        #pragma unroll
        for (int i = 0; i < 4; i++){
            int r = bm + ih*64 + tr*4 + i;
            #pragma unroll
            for (int jh = 0; jh < 2; jh++){
                #pragma unroll
                for (int j = 0; j < 4; j++){
                    int c = bn + jh*64 + tc*4 + j;
                    float val = acc[ih*4+i][jh*4+j] + bias[c];
                    if (res) val += res[r*N + c];
                    if (act == 1){
                        float x = val;
                        val = 0.5f*x*(1.f + tanhf(0.7978845608028654f*(x + 0.044715f*x*x*x)));
                    } else if (act == 2){
                        val = tanhf(val);
                    }
                    C[r*N + c] = val;
                }
            }
        }
    }
}

// ---------------- phi (FAVOR+) : register-tiled GEMM [32 rows x 288 m], K=64 ----------------
// Each block: one (b,h), 32 s-rows. tr=t>>5 (8 groups x 4 rows), tc=t&31 (m lanes, 9 cols).
__global__ __launch_bounds__(256)
void phi_q_kernel(const float* __restrict__ q, const float* __restrict__ proj,
                  float* __restrict__ qp){
    __shared__ float As[16][33];
    __shared__ float Ps[16][289];
    __shared__ float sdiag[32];
    int b = blockIdx.z, h = blockIdx.y, s0 = blockIdx.x*32;
    int bh = b*Hc + h;
    int t = threadIdx.x;
    int tr = t >> 5, tc = t & 31;
    float acc[4][9] = {};
    float dsum = 0.f;
    for (int k0 = 0; k0 < 64; k0 += 16){
        #pragma unroll
        for (int it = 0; it < 2; it++){
            int idx = t + it*256;
            int r = idx >> 4, e = idx & 15;
            As[e][r] = q[(b*Sc + s0 + r)*Dc + h*DHc + k0 + e];
        }
        #pragma unroll
        for (int it = 0; it < 18; it++){
            int idx = t + it*256;
            int m = idx >> 4, e = idx & 15;
            Ps[e][m] = (m < Mc) ? proj[m*DHc + k0 + e] : 0.f;
        }
        __syncthreads();
        if (t < 32){
            #pragma unroll
            for (int e = 0; e < 16; e++){ float x = As[e][t]; dsum += x*x; }
        }
        #pragma unroll
        for (int e = 0; e < 16; e++){
            float a[4], p[9];
            #pragma unroll
            for (int i = 0; i < 4; i++) a[i] = As[e][tr*4 + i];
            #pragma unroll
            for (int j = 0; j < 9; j++) p[j] = Ps[e][tc + 32*j];
            #pragma unroll
            for (int i = 0; i < 4; i++)
                #pragma unroll
                for (int j = 0; j < 9; j++)
                    acc[i][j] += a[i]*p[j];
        }
        __syncthreads();
    }
    if (t < 32) sdiag[t] = dsum*DIAG_SCALE;
    __syncthreads();
    #pragma unroll
    for (int i = 0; i < 4; i++){
        float mx = -1e30f;
        #pragma unroll
        for (int j = 0; j < 9; j++){
            int m = tc + 32*j;
            float d = acc[i][j]*DN_CONST;
            acc[i][j] = d;
            if (m < Mc) mx = fmaxf(mx, d);
        }
        #pragma unroll
        for (int o = 16; o; o >>= 1) mx = fmaxf(mx, __shfl_xor_sync(0xffffffffu, mx, o));
        int r = tr*4 + i;
        float dg = sdiag[r];
        long base = ((long)bh*Sc + s0 + r)*Mc;
        #pragma unroll
        for (int j = 0; j < 9; j++){
            int m = tc + 32*j;
            if (m < Mc)
                qp[base + m] = RATIO_CONST*(expf(acc[i][j] - dg - mx) + PHI_EPS);
        }
    }
}

__global__ void reset_kmax_kernel(){ g_kmax = __int_as_float(0xff800000); }

__global__ __launch_bounds__(256)
void phi_k1_kernel(const float* __restrict__ kin, const float* __restrict__ proj,
                   float* __restrict__ kp, float* __restrict__ diag){
    __shared__ float As[16][33];
    __shared__ float Ps[16][289];
    __shared__ float wmax[8];
    int b = blockIdx.z, h = blockIdx.y, s0 = blockIdx.x*32;
    int bh = b*Hc + h;
    int t = threadIdx.x;
    int tr = t >> 5, tc = t & 31;
    float acc[4][9] = {};
    float dsum = 0.f;
    for (int k0 = 0; k0 < 64; k0 += 16){
        #pragma unroll
        for (int it = 0; it < 2; it++){
            int idx = t + it*256;
            int r = idx >> 4, e = idx & 15;
            As[e][r] = kin[(b*Sc + s0 + r)*Dc + h*DHc + k0 + e];
        }
        #pragma unroll
        for (int it = 0; it < 18; it++){
            int idx = t + it*256;
            int m = idx >> 4, e = idx & 15;
            Ps[e][m] = (m < Mc) ? proj[m*DHc + k0 + e] : 0.f;
        }
        __syncthreads();
        if (t < 32){
            #pragma unroll
            for (int e = 0; e < 16; e++){ float x = As[e][t]; dsum += x*x; }
        }
        #pragma unroll
        for (int e = 0; e < 16; e++){
            float a[4], p[9];
            #pragma unroll
            for (int i = 0; i < 4; i++) a[i] = As[e][tr*4 + i];
            #pragma unroll
            for (int j = 0; j < 9; j++) p[j] = Ps[e][tc + 32*j];
            #pragma unroll
            for (int i = 0; i < 4; i++)
                #pragma unroll
                for (int j = 0; j < 9; j++)
                    acc[i][j] += a[i]*p[j];
        }
        __syncthreads();
    }
    if (t < 32) diag[(long)bh*Sc + s0 + t] = dsum*DIAG_SCALE;
    float lmx = -1e30f;
    #pragma unroll
    for (int i = 0; i < 4; i++){
        int r = tr*4 + i;
        long base = ((long)bh*Sc + s0 + r)*Mc;
        #pragma unroll
        for (int j = 0; j < 9; j++){
            int m = tc + 32*j;
            float d = acc[i][j]*DN_CONST;
            if (m < Mc){ kp[base + m] = d; lmx = fmaxf(lmx, d); }
        }
    }
    #pragma unroll
    for (int o = 16; o; o >>= 1) lmx = fmaxf(lmx, __shfl_xor_sync(0xffffffffu, lmx, o));
    if (tc == 0) wmax[tr] = lmx;
    __syncthreads();
    if (t == 0){
        float mx = -1e30f;
        for (int i = 0; i < 8; i++) mx = fmaxf(mx, wmax[i]);
        atomicMaxFloat(&g_kmax, mx);
    }
}

// Key pass 2: elementwise exp with global stabilizer.
__global__ __launch_bounds__(256)
void phi_k2_kernel(float* __restrict__ kp, const float* __restrict__ diag){
    long i = (long)blockIdx.x*256 + threadIdx.x;   // grid sized exactly
    int row = (int)(i / Mc);
    kp[i] = RATIO_CONST*(expf(kp[i] - diag[row] - g_kmax) + PHI_EPS);
}

// ---------------- ctx = kp^T @ v (plus ksum), 2-stage over 8 s-splits ----------------
// Block: 64 m x 64 e for one (bh, split). tr=t>>4 (16 groups x 4 m), tc=t&15 (4 e cols).
__global__ __launch_bounds__(256)
void ctx_part_kernel(const float* __restrict__ kp, const float* __restrict__ v,
                     float* __restrict__ ctxp, float* __restrict__ ksump){
    __shared__ float ks_s[32][68];
    __shared__ float vs[32][64];
    int mt = blockIdx.x, bh = blockIdx.y, sp = blockIdx.z;
    int b = bh >> 2, h = bh & 3;
    int t = threadIdx.x;
    int tr = t >> 4, tc = t & 15;
    float acc[4][4] = {};
    float ks[4] = {};
    int sbeg = sp*(Sc/8);
    for (int s0 = sbeg; s0 < sbeg + Sc/8; s0 += 32){
        #pragma unroll
        for (int it = 0; it < 8; it++){
            int idx = t + it*256;
            int ss = idx >> 6, ml = idx & 63;
            int m = mt*64 + ml;
            ks_s[ss][ml] = (m < Mc) ? kp[((long)bh*Sc + s0 + ss)*Mc + m] : 0.f;
        }
        #pragma unroll
        for (int it = 0; it < 8; it++){
            int idx = t + it*256;
            int ss = idx >> 6, e = idx & 63;
            vs[ss][e] = v[(b*Sc + s0 + ss)*Dc + h*DHc + e];
        }
        __syncthreads();
        #pragma unroll
        for (int ss = 0; ss < 32; ss++){
            float a[4];
            #pragma unroll
            for (int i = 0; i < 4; i++) a[i] = ks_s[ss][tr*4 + i];
            float4 c4 = *(const float4*)(&vs[ss][tc*4]);
            float c[4] = {c4.x, c4.y, c4.z, c4.w};
            #pragma unroll
            for (int i = 0; i < 4; i++){
                #pragma unroll
                for (int j = 0; j < 4; j++) acc[i][j] += a[i]*c[j];
            }
            if (tc == 0){
                #pragma unroll
                for (int i = 0; i < 4; i++) ks[i] += a[i];
            }
        }
        __syncthreads();
    }
    #pragma unroll
    for (int i = 0; i < 4; i++){
        int m = mt*64 + tr*4 + i;
        if (m < Mc){
            float* cp = ctxp + (((long)sp*BHc + bh)*Mc + m)*DHc + tc*4;
            float4 o4 = make_float4(acc[i][0], acc[i][1], acc[i][2], acc[i][3]);
            *(float4*)cp = o4;
            if (tc == 0) ksump[((long)sp*BHc + bh)*Mc + m] = ks[i];
        }
    }
}

__global__ __launch_bounds__(256)
void ctx_reduce_kernel(const float* __restrict__ ctxp, const float* __restrict__ ksump,
                       float* __restrict__ ctx, float* __restrict__ ksum){
    int i = blockIdx.x*256 + threadIdx.x;
    if (i < BHc*Mc*DHc){
        float s = 0.f;
        #pragma unroll
        for (int sp = 0; sp < 8; sp++) s += ctxp[(long)sp*BHc*Mc*DHc + i];
        ctx[i] = s;
    }
    if (i < BHc*Mc){
        float s = 0.f;
        #pragma unroll
        for (int sp = 0; sp < 8; sp++) s += ksump[sp*BHc*Mc + i];
        ksum[i] = s;
    }
}

// ---------------- d_inv: 1 / (qp . ksum), one warp per row ----------------
__global__ __launch_bounds__(256)
void dinv_kernel(const float* __restrict__ qp, const float* __restrict__ ksum,
                 float* __restrict__ dinv){
    int row  = blockIdx.x*8 + (threadIdx.x>>5);
    int lane = threadIdx.x & 31;
    int bh   = row / Sc;
    const float* qr = qp + (long)row*Mc;
    const float* kr = ksum + bh*Mc;
    float a = 0.f;
    for (int m=lane;m<Mc;m+=32) a += qr[m]*kr[m];
    #pragma unroll
    for (int o=16;o;o>>=1) a += __shfl_xor_sync(0xffffffffu,a,o);
    if (lane == 0) dinv[row] = 1.f/a;
}

// ---------------- attention out: (qp @ ctx) * dinv -> attn[B,S,D] ----------------
// Block: 64 s-rows x 64 e for one bh. tr=t>>4 (16 x 4 rows), tc=t&15 (4 e cols).
__global__ __launch_bounds__(256)
void attn_out_kernel(const float* __restrict__ qp, const float* __restrict__ ctx,
                     const float* __restrict__ dinv, float* __restrict__ attn){
    __shared__ float qs_t[32][68];
    __shared__ float cs[32][64];
    int bh = blockIdx.y;
    int b = bh >> 2, h = bh & 3;
    int s0 = blockIdx.x*64;
    int t = threadIdx.x;
    int tr = t >> 4, tc = t & 15;
    float acc[4][4] = {};
    for (int m0 = 0; m0 < 288; m0 += 32){
        #pragma unroll
        for (int it = 0; it < 8; it++){
            int idx = t + it*256;
            int s = idx >> 5, mm = idx & 31;
            int m = m0 + mm;
            qs_t[mm][s] = (m < Mc) ? qp[((long)bh*Sc + s0 + s)*Mc + m] : 0.f;
        }
        #pragma unroll
        for (int it = 0; it < 8; it++){
            int idx = t + it*256;
            int mm = idx >> 6, e = idx & 63;
            int m = m0 + mm;
            cs[mm][e] = (m < Mc) ? ctx[((long)bh*Mc + m)*DHc + e] : 0.f;
        }
        __syncthreads();
        #pragma unroll
        for (int mm = 0; mm < 32; mm++){
            float a[4];
            #pragma unroll
            for (int i = 0; i < 4; i++) a[i] = qs_t[mm][tr*4 + i];
            float4 c4 = *(const float4*)(&cs[mm][tc*4]);
            float c[4] = {c4.x, c4.y, c4.z, c4.w};
            #pragma unroll
            for (int i = 0; i < 4; i++)
                #pragma unroll
                for (int j = 0; j < 4; j++) acc[i][j] += a[i]*c[j];
        }
        __syncthreads();
    }
    #pragma unroll
    for (int i = 0; i < 4; i++){
        int s = s0 + tr*4 + i;
        float di = dinv[bh*Sc + s];
        float4 o4 = make_float4(acc[i][0]*di, acc[i][1]*di, acc[i][2]*di, acc[i][3]*di);
        *(float4*)(&attn[(b*Sc + s)*Dc + h*DHc + tc*4]) = o4;
    }
}

// ---------------- pooling ----------------
__global__ __launch_bounds__(256)
void alpha_kernel(const float* __restrict__ e, const float* __restrict__ p2w,
                  const float* __restrict__ p2b, const float* __restrict__ mask,
                  float* __restrict__ alpha){
    int row  = blockIdx.x*8 + (threadIdx.x>>5);
    int lane = threadIdx.x & 31;
    const float* er = e + row*Dc;
    float a = 0.f;
    for (int d=lane; d<Dc; d+=32) a += er[d]*p2w[d];
    #pragma unroll
    for (int o=16;o;o>>=1) a += __shfl_xor_sync(0xffffffffu,a,o);
    if (lane == 0) alpha[row] = expf(a + p2b[0])*mask[row];
}

__global__ __launch_bounds__(256)
void asum_kernel(const float* __restrict__ alpha, float* __restrict__ asum){
    int b = blockIdx.x, t = threadIdx.x;
    float s = 0.f;
    for (int i=t;i<Sc;i+=256) s += alpha[b*Sc + i];
    __shared__ float sa[8];
    #pragma unroll
    for (int o=16;o;o>>=1) s += __shfl_xor_sync(0xffffffffu,s,o);
    if ((t&31)==0) sa[t>>5] = s;
    __syncthreads();
    if (t == 0){ float a=0; for (int i=0;i<8;i++) a += sa[i]; asum[b] = a + 1e-8f; }
}

__global__ __launch_bounds__(256)
void pool_part_kernel(const float* __restrict__ x, const float* __restrict__ alpha,
                      float* __restrict__ pp){
    int b = blockIdx.y, c = blockIdx.x, d = threadIdx.x;
    float acc = 0.f;
    int s0 = c*(Sc/32);
    for (int s=s0;s<s0+Sc/32;s++) acc += x[(b*Sc + s)*Dc + d]*alpha[b*Sc + s];
    pp[(c*Bc + b)*Dc + d] = acc;
}

__global__ __launch_bounds__(256)
void pool_reduce_kernel(const float* __restrict__ pp, const float* __restrict__ asum,
                        float* __restrict__ out){
    int i = blockIdx.x*256 + threadIdx.x;
    if (i < Bc*Dc){
        int b = i / Dc, d = i - b*Dc;
        float s = 0.f;
        #pragma unroll
        for (int c=0;c<32;c++) s += pp[(c*Bc + b)*Dc + d];
        out[i] = s / asum[b];
    }
}

// ---------------- host launcher ----------------
extern "C" void kernel_launch(void* const* d_in, const int* in_sizes, int n_in,
                              void* d_out, int out_size){
    const float* input_embs = (const float*)d_in[0];
    const float* mask   = (const float*)d_in[1];
    const float* pos    = (const float*)d_in[2];
    const float* ln_g   = (const float*)d_in[3];
    const float* ln_b   = (const float*)d_in[4];
    const float* proj   = (const float*)d_in[5];
    const float* Wq     = (const float*)d_in[6];
    const float* bq     = (const float*)d_in[7];
    const float* Wk     = (const float*)d_in[8];
    const float* bk     = (const float*)d_in[9];
    const float* Wv     = (const float*)d_in[10];
    const float* bv     = (const float*)d_in[11];
    const float* Wo     = (const float*)d_in[12];
    const float* bo     = (const float*)d_in[13];
    const float* ln1_g  = (const float*)d_in[14];
    const float* ln1_b  = (const float*)d_in[15];
    const float* W1     = (const float*)d_in[16];
    const float* b1     = (const float*)d_in[17];
    const float* W2     = (const float*)d_in[18];
    const float* b2     = (const float*)d_in[19];
    const float* ln2_g  = (const float*)d_in[20];
    const float* ln2_b  = (const float*)d_in[21];
    const float* p1w    = (const float*)d_in[22];
    const float* p1b    = (const float*)d_in[23];
    const float* p2w    = (const float*)d_in[24];
    const float* p2b    = (const float*)d_in[25];
    float* out = (float*)d_out;

    void* p;
    float *X,*XN,*Q,*Kb,*V,*AT,*HID,*QP,*KP,*DIAG,*DINV,*CTX,*KSUM,*CTXP,*KSUMP,*ALPHA,*ASUM,*PP;
    cudaGetSymbolAddress(&p, g_x);     X     = (float*)p;
    cudaGetSymbolAddress(&p, g_xn);    XN    = (float*)p;
    cudaGetSymbolAddress(&p, g_q);     Q     = (float*)p;
    cudaGetSymbolAddress(&p, g_k);     Kb    = (float*)p;
    cudaGetSymbolAddress(&p, g_v);     V     = (float*)p;
    cudaGetSymbolAddress(&p, g_attn);  AT    = (float*)p;
    cudaGetSymbolAddress(&p, g_hid);   HID   = (float*)p;
    cudaGetSymbolAddress(&p, g_qp);    QP    = (float*)p;
    cudaGetSymbolAddress(&p, g_kp);    KP    = (float*)p;
    cudaGetSymbolAddress(&p, g_diag);  DIAG  = (float*)p;
    cudaGetSymbolAddress(&p, g_dinv);  DINV  = (float*)p;
    cudaGetSymbolAddress(&p, g_ctx);   CTX   = (float*)p;
    cudaGetSymbolAddress(&p, g_ksum);  KSUM  = (float*)p;
    cudaGetSymbolAddress(&p, g_ctxp);  CTXP  = (float*)p;
    cudaGetSymbolAddress(&p, g_ksump); KSUMP = (float*)p;
    cudaGetSymbolAddress(&p, g_alpha); ALPHA = (float*)p;
    cudaGetSymbolAddress(&p, g_asum);  ASUM  = (float*)p;
    cudaGetSymbolAddress(&p, g_poolp); PP    = (float*)p;

    // x = LN(input + pos)
    ln_embed_kernel<<<NROWS, 256>>>(input_embs, pos, ln_g, ln_b, X);

    for (int l = 0; l < Lc; l++){
        const float* prj = proj + l*Mc*DHc;
        // ln1
        ln_kernel<<<NROWS, 256>>>(X, ln1_g + l*Dc, ln1_b + l*Dc, XN);
        // QKV
        gemm_kernel<<<dim3(Dc/128, NROWS/128), 256>>>(XN, Wq + l*Dc*Dc, bq + l*Dc, nullptr, Q,  Dc, Dc, 0);
        gemm_kernel<<<dim3(Dc/128, NROWS/128), 256>>>(XN, Wk + l*Dc*Dc, bk + l*Dc, nullptr, Kb, Dc, Dc, 0);
        gemm_kernel<<<dim3(Dc/128, NROWS/128), 256>>>(XN, Wv + l*Dc*Dc, bv + l*Dc, nullptr, V,  Dc, Dc, 0);
        // phi features
        phi_q_kernel<<<dim3(Sc/32, Hc, Bc), 256>>>(Q, prj, QP);
        reset_kmax_kernel<<<1,1>>>();
        phi_k1_kernel<<<dim3(Sc/32, Hc, Bc), 256>>>(Kb, prj, KP, DIAG);
        phi_k2_kernel<<<(BHc*Sc*Mc)/256, 256>>>(KP, DIAG);
        // ctx + ksum
        ctx_part_kernel<<<dim3((Mc+63)/64, BHc, 8), 256>>>(KP, V, CTXP, KSUMP);
        ctx_reduce_kernel<<<(BHc*Mc*DHc + 255)/256, 256>>>(CTXP, KSUMP, CTX, KSUM);
        // normalizer + output
        dinv_kernel<<<(BHc*Sc)/8, 256>>>(QP, KSUM, DINV);
        attn_out_kernel<<<dim3(Sc/64, BHc), 256>>>(QP, CTX, DINV, AT);
        // x += attn @ Wo + bo
        gemm_kernel<<<dim3(Dc/128, NROWS/128), 256>>>(AT, Wo + l*Dc*Dc, bo + l*Dc, X, X, Dc, Dc, 0);
        // FFN
        ln_kernel<<<NROWS, 256>>>(X, ln2_g + l*Dc, ln2_b + l*Dc, XN);
        gemm_kernel<<<dim3(FFc/128, NROWS/128), 256>>>(XN, W1 + l*Dc*FFc, b1 + l*FFc, nullptr, HID, Dc, FFc, 1);
        gemm_kernel<<<dim3(Dc/128, NROWS/128), 256>>>(HID, W2 + l*FFc*Dc, b2 + l*Dc, X, X, FFc, Dc, 0);
    }

    // attention pooling
    gemm_kernel<<<dim3(Dc/128, NROWS/128), 256>>>(X, p1w, p1b, nullptr, XN, Dc, Dc, 2);
    alpha_kernel<<<NROWS/8, 256>>>(XN, p2w, p2b, mask, ALPHA);
    asum_kernel<<<Bc, 256>>>(ALPHA, ASUM);
    pool_part_kernel<<<dim3(32, Bc), 256>>>(X, ALPHA, PP);
    pool_reduce_kernel<<<(Bc*Dc + 255)/256, 256>>>(PP, ASUM, out);
}

// round 11
// speedup vs baseline: 1.0027x; 1.0027x over previous
#include <cuda_runtime.h>
#include <math.h>

// ---------------- problem constants ----------------
#define Bc   4
#define Sc   4096
#define Dc   256
#define Hc   4
#define DHc  64
#define Mc   266
#define Lc   4
#define NROWS (Bc*Sc)   // 16384
#define FFc  (4*Dc)     // 1024
#define BHc  (Bc*Hc)    // 16

#define DN_CONST    0.3535533905932738f     // 64^-0.25
#define DIAG_SCALE  0.0625f                 // 0.5*dn^2
#define RATIO_CONST 0.06131393394849658f    // 266^-0.5
#define PHI_EPS     1e-4f
#define LN_EPS      1e-12f

// ---------------- scratch (device globals; no allocs) ----------------
__device__ float g_x   [NROWS*Dc];
__device__ float g_xn  [NROWS*Dc];
__device__ float g_q   [NROWS*Dc];
__device__ float g_k   [NROWS*Dc];
__device__ float g_v   [NROWS*Dc];
__device__ float g_attn[NROWS*Dc];
__device__ float g_hid [NROWS*FFc];
__device__ float g_qp  [BHc*Sc*Mc];
__device__ float g_kp  [BHc*Sc*Mc];
__device__ float g_diag[BHc*Sc];
__device__ float g_dinv[BHc*Sc];
__device__ float g_ctx [BHc*Mc*DHc];
__device__ float g_ksum[BHc*Mc];
__device__ float g_ctxp [8*BHc*Mc*DHc];
__device__ float g_ksump[8*BHc*Mc];
__device__ float g_alpha[NROWS];
__device__ float g_asum [Bc];
__device__ float g_poolp[32*Bc*Dc];
__device__ float g_kmax;

// ---------------- helpers ----------------
__device__ __forceinline__ void atomicMaxFloat(float* addr, float val){
    if (val >= 0.f) atomicMax((int*)addr, __float_as_int(val));
    else            atomicMin((unsigned int*)addr, __float_as_uint(val));
}

// ---------------- LayerNorm kernels (one block per row, 256 threads) ----------------
__global__ __launch_bounds__(256)
void ln_embed_kernel(const float* __restrict__ emb, const float* __restrict__ pos,
                     const float* __restrict__ gam, const float* __restrict__ bet,
                     float* __restrict__ out){
    int row = blockIdx.x;
    int t   = threadIdx.x;
    float v = emb[row*Dc + t] + pos[(row & (Sc-1))*Dc + t];
    float s1 = v, s2 = v*v;
    __shared__ float sa[8], sb[8];
    #pragma unroll
    for (int o=16;o;o>>=1){ s1 += __shfl_xor_sync(0xffffffffu,s1,o); s2 += __shfl_xor_sync(0xffffffffu,s2,o); }
    if ((t&31)==0){ sa[t>>5]=s1; sb[t>>5]=s2; }
    __syncthreads();
    if (t==0){ float a=0,b=0; for(int i=0;i<8;i++){a+=sa[i]; b+=sb[i];} sa[0]=a; sb[0]=b; }
    __syncthreads();
    float mu  = sa[0]*(1.f/Dc);
    float var = sb[0]*(1.f/Dc) - mu*mu;
    out[row*Dc + t] = (v-mu)*rsqrtf(var+LN_EPS)*gam[t] + bet[t];
}

__global__ __launch_bounds__(256)
void ln_kernel(const float* __restrict__ in,
               const float* __restrict__ gam, const float* __restrict__ bet,
               float* __restrict__ out){
    int row = blockIdx.x;
    int t   = threadIdx.x;
    float v = in[row*Dc + t];
    float s1 = v, s2 = v*v;
    __shared__ float sa[8], sb[8];
    #pragma unroll
    for (int o=16;o;o>>=1){ s1 += __shfl_xor_sync(0xffffffffu,s1,o); s2 += __shfl_xor_sync(0xffffffffu,s2,o); }
    if ((t&31)==0){ sa[t>>5]=s1; sb[t>>5]=s2; }
    __syncthreads();
    if (t==0){ float a=0,b=0; for(int i=0;i<8;i++){a+=sa[i]; b+=sb[i];} sa[0]=a; sb[0]=b; }
    __syncthreads();
    float mu  = sa[0]*(1.f/Dc);
    float var = sb[0]*(1.f/Dc) - mu*mu;
    out[row*Dc + t] = (v-mu)*rsqrtf(var+LN_EPS)*gam[t] + bet[t];
}

// ---------------- SGEMM 128x128x8, 8x8 microtile: C = act(A@W + bias [+ res]) ----------------
// A[R,K] row-major, W[K,N] row-major. 256 threads. K%8==0, N%128==0, R%128==0.
__global__ __launch_bounds__(256)
void gemm_kernel(const float* __restrict__ A, const float* __restrict__ W,
                 const float* __restrict__ bias, const float* __restrict__ res,
                 float* __restrict__ C, int K, int N, int act){
    __shared__ float As[8][132];
    __shared__ float Bs[8][128];
    int bm = blockIdx.y * 128;
    int bn = blockIdx.x * 128;
    int tid = threadIdx.x;
    int tr = tid >> 4;         // 0..15
    int tc = tid & 15;         // 0..15
    // A loader: 128 rows x 8 k, float4 along k
    int lar = tid >> 1, lak = (tid & 1) * 4;
    // B loader: 8 rows x 128 cols, float4 along cols
    int lbk = tid >> 5, lbc = (tid & 31) * 4;
    const float* Aptr = A + (bm + lar)*K + lak;
    const float* Wptr = W + lbk*N + bn + lbc;
    float acc[8][8] = {};
    for (int k0 = 0; k0 < K; k0 += 8){
        float4 a4 = *(const float4*)(Aptr + k0);
        As[lak+0][lar] = a4.x; As[lak+1][lar] = a4.y;
        As[lak+2][lar] = a4.z; As[lak+3][lar] = a4.w;
        *(float4*)(&Bs[lbk][lbc]) = *(const float4*)(Wptr + k0*N);
        __syncthreads();
        #pragma unroll
        for (int k = 0; k < 8; k++){
            float a[8], b[8];
            *(float4*)(a)   = *(const float4*)(&As[k][tr*4]);
            *(float4*)(a+4) = *(const float4*)(&As[k][64 + tr*4]);
            *(float4*)(b)   = *(const float4*)(&Bs[k][tc*4]);
            *(float4*)(b+4) = *(const float4*)(&Bs[k][64 + tc*4]);
            #pragma unroll
            for (int i = 0; i < 8; i++)
                #pragma unroll
                for (int j = 0; j < 8; j++)
                    acc[i][j] += a[i]*b[j];
        }
        __syncthreads();
    }
    #pragma unroll
    for (int ih = 0; ih < 2; ih++){
        #pragma unroll
        for (int i = 0; i < 4; i++){
            int r = bm + ih*64 + tr*4 + i;
            #pragma unroll
            for (int jh = 0; jh < 2; jh++){
                #pragma unroll
                for (int j = 0; j < 4; j++){
                    int c = bn + jh*64 + tc*4 + j;
                    float val = acc[ih*4+i][jh*4+j] + bias[c];
                    if (res) val += res[r*N + c];
                    if (act == 1){
                        float x = val;
                        val = 0.5f*x*(1.f + tanhf(0.7978845608028654f*(x + 0.044715f*x*x*x)));
                    } else if (act == 2){
                        val = tanhf(val);
                    }
                    C[r*N + c] = val;
                }
            }
        }
    }
}

// ---------------- phi (FAVOR+) : register-tiled GEMM [32 rows x 288 m], K=64 ----------------
// Each block: one (b,h), 32 s-rows. tr=t>>5 (8 groups x 4 rows), tc=t&31 (m lanes, 9 cols).
__global__ __launch_bounds__(256)
void phi_q_kernel(const float* __restrict__ q, const float* __restrict__ proj,
                  float* __restrict__ qp){
    __shared__ float As[16][33];
    __shared__ float Ps[16][289];
    __shared__ float sdiag[32];
    int b = blockIdx.z, h = blockIdx.y, s0 = blockIdx.x*32;
    int bh = b*Hc + h;
    int t = threadIdx.x;
    int tr = t >> 5, tc = t & 31;
    float acc[4][9] = {};
    float dsum = 0.f;
    for (int k0 = 0; k0 < 64; k0 += 16){
        #pragma unroll
        for (int it = 0; it < 2; it++){
            int idx = t + it*256;
            int r = idx >> 4, e = idx & 15;
            As[e][r] = q[(b*Sc + s0 + r)*Dc + h*DHc + k0 + e];
        }
        #pragma unroll
        for (int it = 0; it < 18; it++){
            int idx = t + it*256;
            int m = idx >> 4, e = idx & 15;
            Ps[e][m] = (m < Mc) ? proj[m*DHc + k0 + e] : 0.f;
        }
        __syncthreads();
        if (t < 32){
            #pragma unroll
            for (int e = 0; e < 16; e++){ float x = As[e][t]; dsum += x*x; }
        }
        #pragma unroll
        for (int e = 0; e < 16; e++){
            float a[4], p[9];
            #pragma unroll
            for (int i = 0; i < 4; i++) a[i] = As[e][tr*4 + i];
            #pragma unroll
            for (int j = 0; j < 9; j++) p[j] = Ps[e][tc + 32*j];
            #pragma unroll
            for (int i = 0; i < 4; i++)
                #pragma unroll
                for (int j = 0; j < 9; j++)
                    acc[i][j] += a[i]*p[j];
        }
        __syncthreads();
    }
    if (t < 32) sdiag[t] = dsum*DIAG_SCALE;
    __syncthreads();
    #pragma unroll
    for (int i = 0; i < 4; i++){
        float mx = -1e30f;
        #pragma unroll
        for (int j = 0; j < 9; j++){
            int m = tc + 32*j;
            float d = acc[i][j]*DN_CONST;
            acc[i][j] = d;
            if (m < Mc) mx = fmaxf(mx, d);
        }
        #pragma unroll
        for (int o = 16; o; o >>= 1) mx = fmaxf(mx, __shfl_xor_sync(0xffffffffu, mx, o));
        int r = tr*4 + i;
        float dg = sdiag[r];
        long base = ((long)bh*Sc + s0 + r)*Mc;
        #pragma unroll
        for (int j = 0; j < 9; j++){
            int m = tc + 32*j;
            if (m < Mc)
                qp[base + m] = RATIO_CONST*(expf(acc[i][j] - dg - mx) + PHI_EPS);
        }
    }
}

__global__ void reset_kmax_kernel(){ g_kmax = __int_as_float(0xff800000); }

__global__ __launch_bounds__(256)
void phi_k1_kernel(const float* __restrict__ kin, const float* __restrict__ proj,
                   float* __restrict__ kp, float* __restrict__ diag){
    __shared__ float As[16][33];
    __shared__ float Ps[16][289];
    __shared__ float wmax[8];
    int b = blockIdx.z, h = blockIdx.y, s0 = blockIdx.x*32;
    int bh = b*Hc + h;
    int t = threadIdx.x;
    int tr = t >> 5, tc = t & 31;
    float acc[4][9] = {};
    float dsum = 0.f;
    for (int k0 = 0; k0 < 64; k0 += 16){
        #pragma unroll
        for (int it = 0; it < 2; it++){
            int idx = t + it*256;
            int r = idx >> 4, e = idx & 15;
            As[e][r] = kin[(b*Sc + s0 + r)*Dc + h*DHc + k0 + e];
        }
        #pragma unroll
        for (int it = 0; it < 18; it++){
            int idx = t + it*256;
            int m = idx >> 4, e = idx & 15;
            Ps[e][m] = (m < Mc) ? proj[m*DHc + k0 + e] : 0.f;
        }
        __syncthreads();
        if (t < 32){
            #pragma unroll
            for (int e = 0; e < 16; e++){ float x = As[e][t]; dsum += x*x; }
        }
        #pragma unroll
        for (int e = 0; e < 16; e++){
            float a[4], p[9];
            #pragma unroll
            for (int i = 0; i < 4; i++) a[i] = As[e][tr*4 + i];
            #pragma unroll
            for (int j = 0; j < 9; j++) p[j] = Ps[e][tc + 32*j];
            #pragma unroll
            for (int i = 0; i < 4; i++)
                #pragma unroll
                for (int j = 0; j < 9; j++)
                    acc[i][j] += a[i]*p[j];
        }
        __syncthreads();
    }
    if (t < 32) diag[(long)bh*Sc + s0 + t] = dsum*DIAG_SCALE;
    float lmx = -1e30f;
    #pragma unroll
    for (int i = 0; i < 4; i++){
        int r = tr*4 + i;
        long base = ((long)bh*Sc + s0 + r)*Mc;
        #pragma unroll
        for (int j = 0; j < 9; j++){
            int m = tc + 32*j;
            float d = acc[i][j]*DN_CONST;
            if (m < Mc){ kp[base + m] = d; lmx = fmaxf(lmx, d); }
        }
    }
    #pragma unroll
    for (int o = 16; o; o >>= 1) lmx = fmaxf(lmx, __shfl_xor_sync(0xffffffffu, lmx, o));
    if (tc == 0) wmax[tr] = lmx;
    __syncthreads();
    if (t == 0){
        float mx = -1e30f;
        for (int i = 0; i < 8; i++) mx = fmaxf(mx, wmax[i]);
        atomicMaxFloat(&g_kmax, mx);
    }
}

// Key pass 2: elementwise exp with global stabilizer.
__global__ __launch_bounds__(256)
void phi_k2_kernel(float* __restrict__ kp, const float* __restrict__ diag){
    long i = (long)blockIdx.x*256 + threadIdx.x;   // grid sized exactly
    int row = (int)(i / Mc);
    kp[i] = RATIO_CONST*(expf(kp[i] - diag[row] - g_kmax) + PHI_EPS);
}

// ---------------- ctx = kp^T @ v (plus ksum), 2-stage over 8 s-splits ----------------
// Block: 64 m x 64 e for one (bh, split). tr=t>>4 (16 groups x 4 m), tc=t&15 (4 e cols).
__global__ __launch_bounds__(256)
void ctx_part_kernel(const float* __restrict__ kp, const float* __restrict__ v,
                     float* __restrict__ ctxp, float* __restrict__ ksump){
    __shared__ float ks_s[32][68];
    __shared__ float vs[32][64];
    int mt = blockIdx.x, bh = blockIdx.y, sp = blockIdx.z;
    int b = bh >> 2, h = bh & 3;
    int t = threadIdx.x;
    int tr = t >> 4, tc = t & 15;
    float acc[4][4] = {};
    float ks[4] = {};
    int sbeg = sp*(Sc/8);
    for (int s0 = sbeg; s0 < sbeg + Sc/8; s0 += 32){
        #pragma unroll
        for (int it = 0; it < 8; it++){
            int idx = t + it*256;
            int ss = idx >> 6, ml = idx & 63;
            int m = mt*64 + ml;
            ks_s[ss][ml] = (m < Mc) ? kp[((long)bh*Sc + s0 + ss)*Mc + m] : 0.f;
        }
        #pragma unroll
        for (int it = 0; it < 8; it++){
            int idx = t + it*256;
            int ss = idx >> 6, e = idx & 63;
            vs[ss][e] = v[(b*Sc + s0 + ss)*Dc + h*DHc + e];
        }
        __syncthreads();
        #pragma unroll
        for (int ss = 0; ss < 32; ss++){
            float a[4];
            #pragma unroll
            for (int i = 0; i < 4; i++) a[i] = ks_s[ss][tr*4 + i];
            float4 c4 = *(const float4*)(&vs[ss][tc*4]);
            float c[4] = {c4.x, c4.y, c4.z, c4.w};
            #pragma unroll
            for (int i = 0; i < 4; i++){
                #pragma unroll
                for (int j = 0; j < 4; j++) acc[i][j] += a[i]*c[j];
            }
            if (tc == 0){
                #pragma unroll
                for (int i = 0; i < 4; i++) ks[i] += a[i];
            }
        }
        __syncthreads();
    }
    #pragma unroll
    for (int i = 0; i < 4; i++){
        int m = mt*64 + tr*4 + i;
        if (m < Mc){
            float* cp = ctxp + (((long)sp*BHc + bh)*Mc + m)*DHc + tc*4;
            float4 o4 = make_float4(acc[i][0], acc[i][1], acc[i][2], acc[i][3]);
            *(float4*)cp = o4;
            if (tc == 0) ksump[((long)sp*BHc + bh)*Mc + m] = ks[i];
        }
    }
}

__global__ __launch_bounds__(256)
void ctx_reduce_kernel(const float* __restrict__ ctxp, const float* __restrict__ ksump,
                       float* __restrict__ ctx, float* __restrict__ ksum){
    int i = blockIdx.x*256 + threadIdx.x;
    if (i < BHc*Mc*DHc){
        float s = 0.f;
        #pragma unroll
        for (int sp = 0; sp < 8; sp++) s += ctxp[(long)sp*BHc*Mc*DHc + i];
        ctx[i] = s;
    }
    if (i < BHc*Mc){
        float s = 0.f;
        #pragma unroll
        for (int sp = 0; sp < 8; sp++) s += ksump[sp*BHc*Mc + i];
        ksum[i] = s;
    }
}

// ---------------- d_inv: 1 / (qp . ksum), one warp per row ----------------
__global__ __launch_bounds__(256)
void dinv_kernel(const float* __restrict__ qp, const float* __restrict__ ksum,
                 float* __restrict__ dinv){
    int row  = blockIdx.x*8 + (threadIdx.x>>5);
    int lane = threadIdx.x & 31;
    int bh   = row / Sc;
    const float* qr = qp + (long)row*Mc;
    const float* kr = ksum + bh*Mc;
    float a = 0.f;
    for (int m=lane;m<Mc;m+=32) a += qr[m]*kr[m];
    #pragma unroll
    for (int o=16;o;o>>=1) a += __shfl_xor_sync(0xffffffffu,a,o);
    if (lane == 0) dinv[row] = 1.f/a;
}

// ---------------- attention out: (qp @ ctx) * dinv -> attn[B,S,D] ----------------
// Block: 64 s-rows x 64 e for one bh. tr=t>>4 (16 x 4 rows), tc=t&15 (4 e cols).
__global__ __launch_bounds__(256)
void attn_out_kernel(const float* __restrict__ qp, const float* __restrict__ ctx,
                     const float* __restrict__ dinv, float* __restrict__ attn){
    __shared__ float qs_t[32][68];
    __shared__ float cs[32][64];
    int bh = blockIdx.y;
    int b = bh >> 2, h = bh & 3;
    int s0 = blockIdx.x*64;
    int t = threadIdx.x;
    int tr = t >> 4, tc = t & 15;
    float acc[4][4] = {};
    for (int m0 = 0; m0 < 288; m0 += 32){
        #pragma unroll
        for (int it = 0; it < 8; it++){
            int idx = t + it*256;
            int s = idx >> 5, mm = idx & 31;
            int m = m0 + mm;
            qs_t[mm][s] = (m < Mc) ? qp[((long)bh*Sc + s0 + s)*Mc + m] : 0.f;
        }
        #pragma unroll
        for (int it = 0; it < 8; it++){
            int idx = t + it*256;
            int mm = idx >> 6, e = idx & 63;
            int m = m0 + mm;
            cs[mm][e] = (m < Mc) ? ctx[((long)bh*Mc + m)*DHc + e] : 0.f;
        }
        __syncthreads();
        #pragma unroll
        for (int mm = 0; mm < 32; mm++){
            float a[4];
            #pragma unroll
            for (int i = 0; i < 4; i++) a[i] = qs_t[mm][tr*4 + i];
            float4 c4 = *(const float4*)(&cs[mm][tc*4]);
            float c[4] = {c4.x, c4.y, c4.z, c4.w};
            #pragma unroll
            for (int i = 0; i < 4; i++)
                #pragma unroll
                for (int j = 0; j < 4; j++) acc[i][j] += a[i]*c[j];
        }
        __syncthreads();
    }
    #pragma unroll
    for (int i = 0; i < 4; i++){
        int s = s0 + tr*4 + i;
        float di = dinv[bh*Sc + s];
        float4 o4 = make_float4(acc[i][0]*di, acc[i][1]*di, acc[i][2]*di, acc[i][3]*di);
        *(float4*)(&attn[(b*Sc + s)*Dc + h*DHc + tc*4]) = o4;
    }
}

// ---------------- pooling ----------------
__global__ __launch_bounds__(256)
void alpha_kernel(const float* __restrict__ e, const float* __restrict__ p2w,
                  const float* __restrict__ p2b, const float* __restrict__ mask,
                  float* __restrict__ alpha){
    int row  = blockIdx.x*8 + (threadIdx.x>>5);
    int lane = threadIdx.x & 31;
    const float* er = e + row*Dc;
    float a = 0.f;
    for (int d=lane; d<Dc; d+=32) a += er[d]*p2w[d];
    #pragma unroll
    for (int o=16;o;o>>=1) a += __shfl_xor_sync(0xffffffffu,a,o);
    if (lane == 0) alpha[row] = expf(a + p2b[0])*mask[row];
}

__global__ __launch_bounds__(256)
void asum_kernel(const float* __restrict__ alpha, float* __restrict__ asum){
    int b = blockIdx.x, t = threadIdx.x;
    float s = 0.f;
    for (int i=t;i<Sc;i+=256) s += alpha[b*Sc + i];
    __shared__ float sa[8];
    #pragma unroll
    for (int o=16;o;o>>=1) s += __shfl_xor_sync(0xffffffffu,s,o);
    if ((t&31)==0) sa[t>>5] = s;
    __syncthreads();
    if (t == 0){ float a=0; for (int i=0;i<8;i++) a += sa[i]; asum[b] = a + 1e-8f; }
}

__global__ __launch_bounds__(256)
void pool_part_kernel(const float* __restrict__ x, const float* __restrict__ alpha,
                      float* __restrict__ pp){
    int b = blockIdx.y, c = blockIdx.x, d = threadIdx.x;
    float acc = 0.f;
    int s0 = c*(Sc/32);
    for (int s=s0;s<s0+Sc/32;s++) acc += x[(b*Sc + s)*Dc + d]*alpha[b*Sc + s];
    pp[(c*Bc + b)*Dc + d] = acc;
}

__global__ __launch_bounds__(256)
void pool_reduce_kernel(const float* __restrict__ pp, const float* __restrict__ asum,
                        float* __restrict__ out){
    int i = blockIdx.x*256 + threadIdx.x;
    if (i < Bc*Dc){
        int b = i / Dc, d = i - b*Dc;
        float s = 0.f;
        #pragma unroll
        for (int c=0;c<32;c++) s += pp[(c*Bc + b)*Dc + d];
        out[i] = s / asum[b];
    }
}

// ---------------- host launcher ----------------
extern "C" void kernel_launch(void* const* d_in, const int* in_sizes, int n_in,
                              void* d_out, int out_size){
    const float* input_embs = (const float*)d_in[0];
    const float* mask   = (const float*)d_in[1];
    const float* pos    = (const float*)d_in[2];
    const float* ln_g   = (const float*)d_in[3];
    const float* ln_b   = (const float*)d_in[4];
    const float* proj   = (const float*)d_in[5];
    const float* Wq     = (const float*)d_in[6];
    const float* bq     = (const float*)d_in[7];
    const float* Wk     = (const float*)d_in[8];
    const float* bk     = (const float*)d_in[9];
    const float* Wv     = (const float*)d_in[10];
    const float* bv     = (const float*)d_in[11];
    const float* Wo     = (const float*)d_in[12];
    const float* bo     = (const float*)d_in[13];
    const float* ln1_g  = (const float*)d_in[14];
    const float* ln1_b  = (const float*)d_in[15];
    const float* W1     = (const float*)d_in[16];
    const float* b1     = (const float*)d_in[17];
    const float* W2     = (const float*)d_in[18];
    const float* b2     = (const float*)d_in[19];
    const float* ln2_g  = (const float*)d_in[20];
    const float* ln2_b  = (const float*)d_in[21];
    const float* p1w    = (const float*)d_in[22];
    const float* p1b    = (const float*)d_in[23];
    const float* p2w    = (const float*)d_in[24];
    const float* p2b    = (const float*)d_in[25];
    float* out = (float*)d_out;

    void* p;
    float *X,*XN,*Q,*Kb,*V,*AT,*HID,*QP,*KP,*DIAG,*DINV,*CTX,*KSUM,*CTXP,*KSUMP,*ALPHA,*ASUM,*PP;
    cudaGetSymbolAddress(&p, g_x);     X     = (float*)p;
    cudaGetSymbolAddress(&p, g_xn);    XN    = (float*)p;
    cudaGetSymbolAddress(&p, g_q);     Q     = (float*)p;
    cudaGetSymbolAddress(&p, g_k);     Kb    = (float*)p;
    cudaGetSymbolAddress(&p, g_v);     V     = (float*)p;
    cudaGetSymbolAddress(&p, g_attn);  AT    = (float*)p;
    cudaGetSymbolAddress(&p, g_hid);   HID   = (float*)p;
    cudaGetSymbolAddress(&p, g_qp);    QP    = (float*)p;
    cudaGetSymbolAddress(&p, g_kp);    KP    = (float*)p;
    cudaGetSymbolAddress(&p, g_diag);  DIAG  = (float*)p;
    cudaGetSymbolAddress(&p, g_dinv);  DINV  = (float*)p;
    cudaGetSymbolAddress(&p, g_ctx);   CTX   = (float*)p;
    cudaGetSymbolAddress(&p, g_ksum);  KSUM  = (float*)p;
    cudaGetSymbolAddress(&p, g_ctxp);  CTXP  = (float*)p;
    cudaGetSymbolAddress(&p, g_ksump); KSUMP = (float*)p;
    cudaGetSymbolAddress(&p, g_alpha); ALPHA = (float*)p;
    cudaGetSymbolAddress(&p, g_asum);  ASUM  = (float*)p;
    cudaGetSymbolAddress(&p, g_poolp); PP    = (float*)p;

    // x = LN(input + pos)
    ln_embed_kernel<<<NROWS, 256>>>(input_embs, pos, ln_g, ln_b, X);

    for (int l = 0; l < Lc; l++){
        const float* prj = proj + l*Mc*DHc;
        // ln1
        ln_kernel<<<NROWS, 256>>>(X, ln1_g + l*Dc, ln1_b + l*Dc, XN);
        // QKV
        gemm_kernel<<<dim3(Dc/128, NROWS/128), 256>>>(XN, Wq + l*Dc*Dc, bq + l*Dc, nullptr, Q,  Dc, Dc, 0);
        gemm_kernel<<<dim3(Dc/128, NROWS/128), 256>>>(XN, Wk + l*Dc*Dc, bk + l*Dc, nullptr, Kb, Dc, Dc, 0);
        gemm_kernel<<<dim3(Dc/128, NROWS/128), 256>>>(XN, Wv + l*Dc*Dc, bv + l*Dc, nullptr, V,  Dc, Dc, 0);
        // phi features
        phi_q_kernel<<<dim3(Sc/32, Hc, Bc), 256>>>(Q, prj, QP);
        reset_kmax_kernel<<<1,1>>>();
        phi_k1_kernel<<<dim3(Sc/32, Hc, Bc), 256>>>(Kb, prj, KP, DIAG);
        phi_k2_kernel<<<(BHc*Sc*Mc)/256, 256>>>(KP, DIAG);
        // ctx + ksum
        ctx_part_kernel<<<dim3((Mc+63)/64, BHc, 8), 256>>>(KP, V, CTXP, KSUMP);
        ctx_reduce_kernel<<<(BHc*Mc*DHc + 255)/256, 256>>>(CTXP, KSUMP, CTX, KSUM);
        // normalizer + output
        dinv_kernel<<<(BHc*Sc)/8, 256>>>(QP, KSUM, DINV);
        attn_out_kernel<<<dim3(Sc/64, BHc), 256>>>(QP, CTX, DINV, AT);
        // x += attn @ Wo + bo
        gemm_kernel<<<dim3(Dc/128, NROWS/128), 256>>>(AT, Wo + l*Dc*Dc, bo + l*Dc, X, X, Dc, Dc, 0);
        // FFN
        ln_kernel<<<NROWS, 256>>>(X, ln2_g + l*Dc, ln2_b + l*Dc, XN);
        gemm_kernel<<<dim3(FFc/128, NROWS/128), 256>>>(XN, W1 + l*Dc*FFc, b1 + l*FFc, nullptr, HID, Dc, FFc, 1);
        gemm_kernel<<<dim3(Dc/128, NROWS/128), 256>>>(HID, W2 + l*FFc*Dc, b2 + l*Dc, X, X, FFc, Dc, 0);
    }

    // attention pooling
    gemm_kernel<<<dim3(Dc/128, NROWS/128), 256>>>(X, p1w, p1b, nullptr, XN, Dc, Dc, 2);
    alpha_kernel<<<NROWS/8, 256>>>(XN, p2w, p2b, mask, ALPHA);
    asum_kernel<<<Bc, 256>>>(ALPHA, ASUM);
    pool_part_kernel<<<dim3(32, Bc), 256>>>(X, ALPHA, PP);
    pool_reduce_kernel<<<(Bc*Dc + 255)/256, 256>>>(PP, ASUM, out);
}

// round 15
// speedup vs baseline: 1.0937x; 1.0908x over previous
#include <cuda_runtime.h>
#include <math.h>
#include <mma.h>
using namespace nvcuda;

// ---------------- problem constants ----------------
#define Bc   4
#define Sc   4096
#define Dc   256
#define Hc   4
#define DHc  64
#define Mc   266
#define Lc   4
#define NROWS (Bc*Sc)   // 16384
#define FFc  (4*Dc)     // 1024
#define BHc  (Bc*Hc)    // 16

#define DN_CONST    0.3535533905932738f     // 64^-0.25
#define DIAG_SCALE  0.0625f                 // 0.5*dn^2
#define RATIO_CONST 0.06131393394849658f    // 266^-0.5
#define PHI_EPS     1e-4f
#define LN_EPS      1e-12f

// ---------------- scratch (device globals; no allocs) ----------------
__device__ float g_x   [NROWS*Dc];
__device__ float g_xn  [NROWS*Dc];
__device__ float g_q   [NROWS*Dc];
__device__ float g_k   [NROWS*Dc];
__device__ float g_v   [NROWS*Dc];
__device__ float g_attn[NROWS*Dc];
__device__ float g_hid [NROWS*FFc];
__device__ float g_qp  [BHc*Sc*Mc];
__device__ float g_kp  [BHc*Sc*Mc];
__device__ float g_diag[BHc*Sc];
__device__ float g_dinv[BHc*Sc];
__device__ float g_ctx [BHc*Mc*DHc];
__device__ float g_ksum[BHc*Mc];
__device__ float g_ctxp [8*BHc*Mc*DHc];
__device__ float g_ksump[8*BHc*Mc];
__device__ float g_alpha[NROWS];
__device__ float g_asum [Bc];
__device__ float g_poolp[32*Bc*Dc];
__device__ float g_kmax;

// ---------------- helpers ----------------
__device__ __forceinline__ void atomicMaxFloat(float* addr, float val){
    if (val >= 0.f) atomicMax((int*)addr, __float_as_int(val));
    else            atomicMin((unsigned int*)addr, __float_as_uint(val));
}

// ---------------- LayerNorm kernels (one block per row, 256 threads) ----------------
__global__ __launch_bounds__(256)
void ln_embed_kernel(const float* __restrict__ emb, const float* __restrict__ pos,
                     const float* __restrict__ gam, const float* __restrict__ bet,
                     float* __restrict__ out){
    int row = blockIdx.x;
    int t   = threadIdx.x;
    float v = emb[row*Dc + t] + pos[(row & (Sc-1))*Dc + t];
    float s1 = v, s2 = v*v;
    __shared__ float sa[8], sb[8];
    #pragma unroll
    for (int o=16;o;o>>=1){ s1 += __shfl_xor_sync(0xffffffffu,s1,o); s2 += __shfl_xor_sync(0xffffffffu,s2,o); }
    if ((t&31)==0){ sa[t>>5]=s1; sb[t>>5]=s2; }
    __syncthreads();
    if (t==0){ float a=0,b=0; for(int i=0;i<8;i++){a+=sa[i]; b+=sb[i];} sa[0]=a; sb[0]=b; }
    __syncthreads();
    float mu  = sa[0]*(1.f/Dc);
    float var = sb[0]*(1.f/Dc) - mu*mu;
    out[row*Dc + t] = (v-mu)*rsqrtf(var+LN_EPS)*gam[t] + bet[t];
}

__global__ __launch_bounds__(256)
void ln_kernel(const float* __restrict__ in,
               const float* __restrict__ gam, const float* __restrict__ bet,
               float* __restrict__ out){
    int row = blockIdx.x;
    int t   = threadIdx.x;
    float v = in[row*Dc + t];
    float s1 = v, s2 = v*v;
    __shared__ float sa[8], sb[8];
    #pragma unroll
    for (int o=16;o;o>>=1){ s1 += __shfl_xor_sync(0xffffffffu,s1,o); s2 += __shfl_xor_sync(0xffffffffu,s2,o); }
    if ((t&31)==0){ sa[t>>5]=s1; sb[t>>5]=s2; }
    __syncthreads();
    if (t==0){ float a=0,b=0; for(int i=0;i<8;i++){a+=sa[i]; b+=sb[i];} sa[0]=a; sb[0]=b; }
    __syncthreads();
    float mu  = sa[0]*(1.f/Dc);
    float var = sb[0]*(1.f/Dc) - mu*mu;
    out[row*Dc + t] = (v-mu)*rsqrtf(var+LN_EPS)*gam[t] + bet[t];
}

// ---------------- tf32 wmma GEMM 128x128x32: C = act(A@W + bias [+ res]) ----------------
// A[R,K] row-major, W[K,N] row-major. 256 thr = 8 warps in 4(m) x 2(n) layout.
// Warp tile 32x64 = 2x4 wmma m16n16k8 tiles. K%32==0, N%128==0, R%128==0.
__global__ __launch_bounds__(256)
void gemm_kernel(const float* __restrict__ A, const float* __restrict__ W,
                 const float* __restrict__ bias, const float* __restrict__ res,
                 float* __restrict__ C, int K, int N, int act){
    __shared__ float smem[8832];
    float (*As)[36]  = (float(*)[36])smem;           // 128 x 36  (4608 floats)
    float (*Bs)[132] = (float(*)[132])(smem + 4608); // 32 x 132  (4224 floats)
    float (*Cs)[132] = (float(*)[132])smem;          // 64 x 132  (8448, reuses As/Bs)

    int bm = blockIdx.y * 128;
    int bn = blockIdx.x * 128;
    int tid = threadIdx.x;
    int wid = tid >> 5;
    int warp_m = wid >> 1;      // 0..3 -> rows 32*warp_m
    int warp_n = wid & 1;       // 0..1 -> cols 64*warp_n

    wmma::fragment<wmma::accumulator,16,16,8,float> acc[2][4];
    #pragma unroll
    for (int i=0;i<2;i++)
        #pragma unroll
        for (int j=0;j<4;j++) wmma::fill_fragment(acc[i][j], 0.f);

    for (int k0 = 0; k0 < K; k0 += 32){
        #pragma unroll
        for (int i=0;i<4;i++){                       // A: 128x32
            int lin = tid + i*256;
            int r = lin >> 3, k4 = (lin & 7)*4;
            *(float4*)&As[r][k4] = *(const float4*)&A[(bm+r)*K + k0 + k4];
        }
        #pragma unroll
        for (int i=0;i<4;i++){                       // B: 32x128
            int lin = tid + i*256;
            int kr = lin >> 5, c4 = (lin & 31)*4;
            *(float4*)&Bs[kr][c4] = *(const float4*)&W[(k0+kr)*N + bn + c4];
        }
        __syncthreads();
        #pragma unroll
        for (int kk = 0; kk < 32; kk += 8){
            wmma::fragment<wmma::matrix_a,16,16,8,wmma::precision::tf32,wmma::row_major> af[2];
            wmma::fragment<wmma::matrix_b,16,16,8,wmma::precision::tf32,wmma::row_major> bf[4];
            #pragma unroll
            for (int i=0;i<2;i++){
                wmma::load_matrix_sync(af[i], &As[warp_m*32 + i*16][kk], 36);
                #pragma unroll
                for (int e=0;e<af[i].num_elements;e++) af[i].x[e] = wmma::__float_to_tf32(af[i].x[e]);
            }
            #pragma unroll
            for (int j=0;j<4;j++){
                wmma::load_matrix_sync(bf[j], &Bs[kk][warp_n*64 + j*16], 132);
                #pragma unroll
                for (int e=0;e<bf[j].num_elements;e++) bf[j].x[e] = wmma::__float_to_tf32(bf[j].x[e]);
            }
            #pragma unroll
            for (int i=0;i<2;i++)
                #pragma unroll
                for (int j=0;j<4;j++)
                    wmma::mma_sync(acc[i][j], af[i], bf[j], acc[i][j]);
        }
        __syncthreads();
    }
    // epilogue: two phases of 64 rows staged through smem
    #pragma unroll
    for (int phase = 0; phase < 2; phase++){
        if ((warp_m >> 1) == phase){
            int rbase = (warp_m & 1)*32;
            #pragma unroll
            for (int i=0;i<2;i++)
                #pragma unroll
                for (int j=0;j<4;j++)
                    wmma::store_matrix_sync(&Cs[rbase + i*16][warp_n*64 + j*16],
                                            acc[i][j], 132, wmma::mem_row_major);
        }
        __syncthreads();
        #pragma unroll
        for (int i=0;i<8;i++){
            int lin = tid + i*256;
            int r = lin >> 5, c4 = (lin & 31)*4;
            int rg = bm + phase*64 + r;
            float4 v4 = *(float4*)&Cs[r][c4];
            float vv[4] = {v4.x, v4.y, v4.z, v4.w};
            float rr[4] = {0.f,0.f,0.f,0.f};
            if (res){
                float4 r4 = *(const float4*)&res[rg*N + bn + c4];
                rr[0]=r4.x; rr[1]=r4.y; rr[2]=r4.z; rr[3]=r4.w;
            }
            float4 o4;
            float* ov = (float*)&o4;
            #pragma unroll
            for (int j=0;j<4;j++){
                int c = bn + c4 + j;
                float val = vv[j] + bias[c] + rr[j];
                if (act == 1){
                    float x = val;
                    val = 0.5f*x*(1.f + tanhf(0.7978845608028654f*(x + 0.044715f*x*x*x)));
                } else if (act == 2){
                    val = tanhf(val);
                }
                ov[j] = val;
            }
            *(float4*)&C[rg*N + bn + c4] = o4;
        }
        __syncthreads();
    }
}

// ---------------- phi (FAVOR+) : register-tiled GEMM [32 rows x 288 m], K=64 ----------------
__global__ __launch_bounds__(256)
void phi_q_kernel(const float* __restrict__ q, const float* __restrict__ proj,
                  float* __restrict__ qp){
    __shared__ float As[16][33];
    __shared__ float Ps[16][289];
    __shared__ float sdiag[32];
    int b = blockIdx.z, h = blockIdx.y, s0 = blockIdx.x*32;
    int bh = b*Hc + h;
    int t = threadIdx.x;
    int tr = t >> 5, tc = t & 31;
    float acc[4][9] = {};
    float dsum = 0.f;
    for (int k0 = 0; k0 < 64; k0 += 16){
        #pragma unroll
        for (int it = 0; it < 2; it++){
            int idx = t + it*256;
            int r = idx >> 4, e = idx & 15;
            As[e][r] = q[(b*Sc + s0 + r)*Dc + h*DHc + k0 + e];
        }
        #pragma unroll
        for (int it = 0; it < 18; it++){
            int idx = t + it*256;
            int m = idx >> 4, e = idx & 15;
            Ps[e][m] = (m < Mc) ? proj[m*DHc + k0 + e] : 0.f;
        }
        __syncthreads();
        if (t < 32){
            #pragma unroll
            for (int e = 0; e < 16; e++){ float x = As[e][t]; dsum += x*x; }
        }
        #pragma unroll
        for (int e = 0; e < 16; e++){
            float a[4], p[9];
            #pragma unroll
            for (int i = 0; i < 4; i++) a[i] = As[e][tr*4 + i];
            #pragma unroll
            for (int j = 0; j < 9; j++) p[j] = Ps[e][tc + 32*j];
            #pragma unroll
            for (int i = 0; i < 4; i++)
                #pragma unroll
                for (int j = 0; j < 9; j++)
                    acc[i][j] += a[i]*p[j];
        }
        __syncthreads();
    }
    if (t < 32) sdiag[t] = dsum*DIAG_SCALE;
    __syncthreads();
    #pragma unroll
    for (int i = 0; i < 4; i++){
        float mx = -1e30f;
        #pragma unroll
        for (int j = 0; j < 9; j++){
            int m = tc + 32*j;
            float d = acc[i][j]*DN_CONST;
            acc[i][j] = d;
            if (m < Mc) mx = fmaxf(mx, d);
        }
        #pragma unroll
        for (int o = 16; o; o >>= 1) mx = fmaxf(mx, __shfl_xor_sync(0xffffffffu, mx, o));
        int r = tr*4 + i;
        float dg = sdiag[r];
        long base = ((long)bh*Sc + s0 + r)*Mc;
        #pragma unroll
        for (int j = 0; j < 9; j++){
            int m = tc + 32*j;
            if (m < Mc)
                qp[base + m] = RATIO_CONST*(expf(acc[i][j] - dg - mx) + PHI_EPS);
        }
    }
}

__global__ void reset_kmax_kernel(){ g_kmax = __int_as_float(0xff800000); }

__global__ __launch_bounds__(256)
void phi_k1_kernel(const float* __restrict__ kin, const float* __restrict__ proj,
                   float* __restrict__ kp, float* __restrict__ diag){
    __shared__ float As[16][33];
    __shared__ float Ps[16][289];
    __shared__ float wmax[8];
    int b = blockIdx.z, h = blockIdx.y, s0 = blockIdx.x*32;
    int bh = b*Hc + h;
    int t = threadIdx.x;
    int tr = t >> 5, tc = t & 31;
    float acc[4][9] = {};
    float dsum = 0.f;
    for (int k0 = 0; k0 < 64; k0 += 16){
        #pragma unroll
        for (int it = 0; it < 2; it++){
            int idx = t + it*256;
            int r = idx >> 4, e = idx & 15;
            As[e][r] = kin[(b*Sc + s0 + r)*Dc + h*DHc + k0 + e];
        }
        #pragma unroll
        for (int it = 0; it < 18; it++){
            int idx = t + it*256;
            int m = idx >> 4, e = idx & 15;
            Ps[e][m] = (m < Mc) ? proj[m*DHc + k0 + e] : 0.f;
        }
        __syncthreads();
        if (t < 32){
            #pragma unroll
            for (int e = 0; e < 16; e++){ float x = As[e][t]; dsum += x*x; }
        }
        #pragma unroll
        for (int e = 0; e < 16; e++){
            float a[4], p[9];
            #pragma unroll
            for (int i = 0; i < 4; i++) a[i] = As[e][tr*4 + i];
            #pragma unroll
            for (int j = 0; j < 9; j++) p[j] = Ps[e][tc + 32*j];
            #pragma unroll
            for (int i = 0; i < 4; i++)
                #pragma unroll
                for (int j = 0; j < 9; j++)
                    acc[i][j] += a[i]*p[j];
        }
        __syncthreads();
    }
    if (t < 32) diag[(long)bh*Sc + s0 + t] = dsum*DIAG_SCALE;
    float lmx = -1e30f;
    #pragma unroll
    for (int i = 0; i < 4; i++){
        int r = tr*4 + i;
        long base = ((long)bh*Sc + s0 + r)*Mc;
        #pragma unroll
        for (int j = 0; j < 9; j++){
            int m = tc + 32*j;
            float d = acc[i][j]*DN_CONST;
            if (m < Mc){ kp[base + m] = d; lmx = fmaxf(lmx, d); }
        }
    }
    #pragma unroll
    for (int o = 16; o; o >>= 1) lmx = fmaxf(lmx, __shfl_xor_sync(0xffffffffu, lmx, o));
    if (tc == 0) wmax[tr] = lmx;
    __syncthreads();
    if (t == 0){
        float mx = -1e30f;
        for (int i = 0; i < 8; i++) mx = fmaxf(mx, wmax[i]);
        atomicMaxFloat(&g_kmax, mx);
    }
}

__global__ __launch_bounds__(256)
void phi_k2_kernel(float* __restrict__ kp, const float* __restrict__ diag){
    long i = (long)blockIdx.x*256 + threadIdx.x;
    int row = (int)(i / Mc);
    kp[i] = RATIO_CONST*(expf(kp[i] - diag[row] - g_kmax) + PHI_EPS);
}

// ---------------- ctx = kp^T @ v (plus ksum), 2-stage over 8 s-splits ----------------
__global__ __launch_bounds__(256)
void ctx_part_kernel(const float* __restrict__ kp, const float* __restrict__ v,
                     float* __restrict__ ctxp, float* __restrict__ ksump){
    __shared__ float ks_s[32][68];
    __shared__ float vs[32][64];
    int mt = blockIdx.x, bh = blockIdx.y, sp = blockIdx.z;
    int b = bh >> 2, h = bh & 3;
    int t = threadIdx.x;
    int tr = t >> 4, tc = t & 15;
    float acc[4][4] = {};
    float ks[4] = {};
    int sbeg = sp*(Sc/8);
    for (int s0 = sbeg; s0 < sbeg + Sc/8; s0 += 32){
        #pragma unroll
        for (int it = 0; it < 8; it++){
            int idx = t + it*256;
            int ss = idx >> 6, ml = idx & 63;
            int m = mt*64 + ml;
            ks_s[ss][ml] = (m < Mc) ? kp[((long)bh*Sc + s0 + ss)*Mc + m] : 0.f;
        }
        #pragma unroll
        for (int it = 0; it < 8; it++){
            int idx = t + it*256;
            int ss = idx >> 6, e = idx & 63;
            vs[ss][e] = v[(b*Sc + s0 + ss)*Dc + h*DHc + e];
        }
        __syncthreads();
        #pragma unroll
        for (int ss = 0; ss < 32; ss++){
            float a[4];
            #pragma unroll
            for (int i = 0; i < 4; i++) a[i] = ks_s[ss][tr*4 + i];
            float4 c4 = *(const float4*)(&vs[ss][tc*4]);
            float c[4] = {c4.x, c4.y, c4.z, c4.w};
            #pragma unroll
            for (int i = 0; i < 4; i++){
                #pragma unroll
                for (int j = 0; j < 4; j++) acc[i][j] += a[i]*c[j];
            }
            if (tc == 0){
                #pragma unroll
                for (int i = 0; i < 4; i++) ks[i] += a[i];
            }
        }
        __syncthreads();
    }
    #pragma unroll
    for (int i = 0; i < 4; i++){
        int m = mt*64 + tr*4 + i;
        if (m < Mc){
            float* cp = ctxp + (((long)sp*BHc + bh)*Mc + m)*DHc + tc*4;
            float4 o4 = make_float4(acc[i][0], acc[i][1], acc[i][2], acc[i][3]);
            *(float4*)cp = o4;
            if (tc == 0) ksump[((long)sp*BHc + bh)*Mc + m] = ks[i];
        }
    }
}

__global__ __launch_bounds__(256)
void ctx_reduce_kernel(const float* __restrict__ ctxp, const float* __restrict__ ksump,
                       float* __restrict__ ctx, float* __restrict__ ksum){
    int i = blockIdx.x*256 + threadIdx.x;
    if (i < BHc*Mc*DHc){
        float s = 0.f;
        #pragma unroll
        for (int sp = 0; sp < 8; sp++) s += ctxp[(long)sp*BHc*Mc*DHc + i];
        ctx[i] = s;
    }
    if (i < BHc*Mc){
        float s = 0.f;
        #pragma unroll
        for (int sp = 0; sp < 8; sp++) s += ksump[sp*BHc*Mc + i];
        ksum[i] = s;
    }
}

// ---------------- d_inv: 1 / (qp . ksum), one warp per row ----------------
__global__ __launch_bounds__(256)
void dinv_kernel(const float* __restrict__ qp, const float* __restrict__ ksum,
                 float* __restrict__ dinv){
    int row  = blockIdx.x*8 + (threadIdx.x>>5);
    int lane = threadIdx.x & 31;
    int bh   = row / Sc;
    const float* qr = qp + (long)row*Mc;
    const float* kr = ksum + bh*Mc;
    float a = 0.f;
    for (int m=lane;m<Mc;m+=32) a += qr[m]*kr[m];
    #pragma unroll
    for (int o=16;o;o>>=1) a += __shfl_xor_sync(0xffffffffu,a,o);
    if (lane == 0) dinv[row] = 1.f/a;
}

// ---------------- attention out: (qp @ ctx) * dinv -> attn[B,S,D] ----------------
__global__ __launch_bounds__(256)
void attn_out_kernel(const float* __restrict__ qp, const float* __restrict__ ctx,
                     const float* __restrict__ dinv, float* __restrict__ attn){
    __shared__ float qs_t[32][68];
    __shared__ float cs[32][64];
    int bh = blockIdx.y;
    int b = bh >> 2, h = bh & 3;
    int s0 = blockIdx.x*64;
    int t = threadIdx.x;
    int tr = t >> 4, tc = t & 15;
    float acc[4][4] = {};
    for (int m0 = 0; m0 < 288; m0 += 32){
        #pragma unroll
        for (int it = 0; it < 8; it++){
            int idx = t + it*256;
            int s = idx >> 5, mm = idx & 31;
            int m = m0 + mm;
            qs_t[mm][s] = (m < Mc) ? qp[((long)bh*Sc + s0 + s)*Mc + m] : 0.f;
        }
        #pragma unroll
        for (int it = 0; it < 8; it++){
            int idx = t + it*256;
            int mm = idx >> 6, e = idx & 63;
            int m = m0 + mm;
            cs[mm][e] = (m < Mc) ? ctx[((long)bh*Mc + m)*DHc + e] : 0.f;
        }
        __syncthreads();
        #pragma unroll
        for (int mm = 0; mm < 32; mm++){
            float a[4];
            #pragma unroll
            for (int i = 0; i < 4; i++) a[i] = qs_t[mm][tr*4 + i];
            float4 c4 = *(const float4*)(&cs[mm][tc*4]);
            float c[4] = {c4.x, c4.y, c4.z, c4.w};
            #pragma unroll
            for (int i = 0; i < 4; i++)
                #pragma unroll
                for (int j = 0; j < 4; j++) acc[i][j] += a[i]*c[j];
        }
        __syncthreads();
    }
    #pragma unroll
    for (int i = 0; i < 4; i++){
        int s = s0 + tr*4 + i;
        float di = dinv[bh*Sc + s];
        float4 o4 = make_float4(acc[i][0]*di, acc[i][1]*di, acc[i][2]*di, acc[i][3]*di);
        *(float4*)(&attn[(b*Sc + s)*Dc + h*DHc + tc*4]) = o4;
    }
}

// ---------------- pooling ----------------
__global__ __launch_bounds__(256)
void alpha_kernel(const float* __restrict__ e, const float* __restrict__ p2w,
                  const float* __restrict__ p2b, const float* __restrict__ mask,
                  float* __restrict__ alpha){
    int row  = blockIdx.x*8 + (threadIdx.x>>5);
    int lane = threadIdx.x & 31;
    const float* er = e + row*Dc;
    float a = 0.f;
    for (int d=lane; d<Dc; d+=32) a += er[d]*p2w[d];
    #pragma unroll
    for (int o=16;o;o>>=1) a += __shfl_xor_sync(0xffffffffu,a,o);
    if (lane == 0) alpha[row] = expf(a + p2b[0])*mask[row];
}

__global__ __launch_bounds__(256)
void asum_kernel(const float* __restrict__ alpha, float* __restrict__ asum){
    int b = blockIdx.x, t = threadIdx.x;
    float s = 0.f;
    for (int i=t;i<Sc;i+=256) s += alpha[b*Sc + i];
    __shared__ float sa[8];
    #pragma unroll
    for (int o=16;o;o>>=1) s += __shfl_xor_sync(0xffffffffu,s,o);
    if ((t&31)==0) sa[t>>5] = s;
    __syncthreads();
    if (t == 0){ float a=0; for (int i=0;i<8;i++) a += sa[i]; asum[b] = a + 1e-8f; }
}

__global__ __launch_bounds__(256)
void pool_part_kernel(const float* __restrict__ x, const float* __restrict__ alpha,
                      float* __restrict__ pp){
    int b = blockIdx.y, c = blockIdx.x, d = threadIdx.x;
    float acc = 0.f;
    int s0 = c*(Sc/32);
    for (int s=s0;s<s0+Sc/32;s++) acc += x[(b*Sc + s)*Dc + d]*alpha[b*Sc + s];
    pp[(c*Bc + b)*Dc + d] = acc;
}

__global__ __launch_bounds__(256)
void pool_reduce_kernel(const float* __restrict__ pp, const float* __restrict__ asum,
                        float* __restrict__ out){
    int i = blockIdx.x*256 + threadIdx.x;
    if (i < Bc*Dc){
        int b = i / Dc, d = i - b*Dc;
        float s = 0.f;
        #pragma unroll
        for (int c=0;c<32;c++) s += pp[(c*Bc + b)*Dc + d];
        out[i] = s / asum[b];
    }
}

// ---------------- host launcher ----------------
extern "C" void kernel_launch(void* const* d_in, const int* in_sizes, int n_in,
                              void* d_out, int out_size){
    const float* input_embs = (const float*)d_in[0];
    const float* mask   = (const float*)d_in[1];
    const float* pos    = (const float*)d_in[2];
    const float* ln_g   = (const float*)d_in[3];
    const float* ln_b   = (const float*)d_in[4];
    const float* proj   = (const float*)d_in[5];
    const float* Wq     = (const float*)d_in[6];
    const float* bq     = (const float*)d_in[7];
    const float* Wk     = (const float*)d_in[8];
    const float* bk     = (const float*)d_in[9];
    const float* Wv     = (const float*)d_in[10];
    const float* bv     = (const float*)d_in[11];
    const float* Wo     = (const float*)d_in[12];
    const float* bo     = (const float*)d_in[13];
    const float* ln1_g  = (const float*)d_in[14];
    const float* ln1_b  = (const float*)d_in[15];
    const float* W1     = (const float*)d_in[16];
    const float* b1     = (const float*)d_in[17];
    const float* W2     = (const float*)d_in[18];
    const float* b2     = (const float*)d_in[19];
    const float* ln2_g  = (const float*)d_in[20];
    const float* ln2_b  = (const float*)d_in[21];
    const float* p1w    = (const float*)d_in[22];
    const float* p1b    = (const float*)d_in[23];
    const float* p2w    = (const float*)d_in[24];
    const float* p2b    = (const float*)d_in[25];
    float* out = (float*)d_out;

    void* p;
    float *X,*XN,*Q,*Kb,*V,*AT,*HID,*QP,*KP,*DIAG,*DINV,*CTX,*KSUM,*CTXP,*KSUMP,*ALPHA,*ASUM,*PP;
    cudaGetSymbolAddress(&p, g_x);     X     = (float*)p;
    cudaGetSymbolAddress(&p, g_xn);    XN    = (float*)p;
    cudaGetSymbolAddress(&p, g_q);     Q     = (float*)p;
    cudaGetSymbolAddress(&p, g_k);     Kb    = (float*)p;
    cudaGetSymbolAddress(&p, g_v);     V     = (float*)p;
    cudaGetSymbolAddress(&p, g_attn);  AT    = (float*)p;
    cudaGetSymbolAddress(&p, g_hid);   HID   = (float*)p;
    cudaGetSymbolAddress(&p, g_qp);    QP    = (float*)p;
    cudaGetSymbolAddress(&p, g_kp);    KP    = (float*)p;
    cudaGetSymbolAddress(&p, g_diag);  DIAG  = (float*)p;
    cudaGetSymbolAddress(&p, g_dinv);  DINV  = (float*)p;
    cudaGetSymbolAddress(&p, g_ctx);   CTX   = (float*)p;
    cudaGetSymbolAddress(&p, g_ksum);  KSUM  = (float*)p;
    cudaGetSymbolAddress(&p, g_ctxp);  CTXP  = (float*)p;
    cudaGetSymbolAddress(&p, g_ksump); KSUMP = (float*)p;
    cudaGetSymbolAddress(&p, g_alpha); ALPHA = (float*)p;
    cudaGetSymbolAddress(&p, g_asum);  ASUM  = (float*)p;
    cudaGetSymbolAddress(&p, g_poolp); PP    = (float*)p;

    // x = LN(input + pos)
    ln_embed_kernel<<<NROWS, 256>>>(input_embs, pos, ln_g, ln_b, X);

    for (int l = 0; l < Lc; l++){
        const float* prj = proj + l*Mc*DHc;
        // ln1
        ln_kernel<<<NROWS, 256>>>(X, ln1_g + l*Dc, ln1_b + l*Dc, XN);
        // QKV
        gemm_kernel<<<dim3(Dc/128, NROWS/128), 256>>>(XN, Wq + l*Dc*Dc, bq + l*Dc, nullptr, Q,  Dc, Dc, 0);
        gemm_kernel<<<dim3(Dc/128, NROWS/128), 256>>>(XN, Wk + l*Dc*Dc, bk + l*Dc, nullptr, Kb, Dc, Dc, 0);
        gemm_kernel<<<dim3(Dc/128, NROWS/128), 256>>>(XN, Wv + l*Dc*Dc, bv + l*Dc, nullptr, V,  Dc, Dc, 0);
        // phi features
        phi_q_kernel<<<dim3(Sc/32, Hc, Bc), 256>>>(Q, prj, QP);
        reset_kmax_kernel<<<1,1>>>();
        phi_k1_kernel<<<dim3(Sc/32, Hc, Bc), 256>>>(Kb, prj, KP, DIAG);
        phi_k2_kernel<<<(BHc*Sc*Mc)/256, 256>>>(KP, DIAG);
        // ctx + ksum
        ctx_part_kernel<<<dim3((Mc+63)/64, BHc, 8), 256>>>(KP, V, CTXP, KSUMP);
        ctx_reduce_kernel<<<(BHc*Mc*DHc + 255)/256, 256>>>(CTXP, KSUMP, CTX, KSUM);
        // normalizer + output
        dinv_kernel<<<(BHc*Sc)/8, 256>>>(QP, KSUM, DINV);
        attn_out_kernel<<<dim3(Sc/64, BHc), 256>>>(QP, CTX, DINV, AT);
        // x += attn @ Wo + bo
        gemm_kernel<<<dim3(Dc/128, NROWS/128), 256>>>(AT, Wo + l*Dc*Dc, bo + l*Dc, X, X, Dc, Dc, 0);
        // FFN
        ln_kernel<<<NROWS, 256>>>(X, ln2_g + l*Dc, ln2_b + l*Dc, XN);
        gemm_kernel<<<dim3(FFc/128, NROWS/128), 256>>>(XN, W1 + l*Dc*FFc, b1 + l*FFc, nullptr, HID, Dc, FFc, 1);
        gemm_kernel<<<dim3(Dc/128, NROWS/128), 256>>>(HID, W2 + l*FFc*Dc, b2 + l*Dc, X, X, FFc, Dc, 0);
    }

    // attention pooling
    gemm_kernel<<<dim3(Dc/128, NROWS/128), 256>>>(X, p1w, p1b, nullptr, XN, Dc, Dc, 2);
    alpha_kernel<<<NROWS/8, 256>>>(XN, p2w, p2b, mask, ALPHA);
    asum_kernel<<<Bc, 256>>>(ALPHA, ASUM);
    pool_part_kernel<<<dim3(32, Bc), 256>>>(X, ALPHA, PP);
    pool_reduce_kernel<<<(Bc*Dc + 255)/256, 256>>>(PP, ASUM, out);
}

// round 16
// speedup vs baseline: 1.1196x; 1.0236x over previous
#include <cuda_runtime.h>
#include <math.h>
#include <mma.h>
using namespace nvcuda;

// ---------------- problem constants ----------------
#define Bc   4
#define Sc   4096
#define Dc   256
#define Hc   4
#define DHc  64
#define Mc   266
#define MP   288           // padded feature count (18*16)
#define Lc   4
#define NROWS (Bc*Sc)   // 16384
#define FFc  (4*Dc)     // 1024
#define BHc  (Bc*Hc)    // 16

#define DN_CONST    0.3535533905932738f     // 64^-0.25
#define DIAG_SCALE  0.0625f                 // 0.5*dn^2
#define RATIO_CONST 0.06131393394849658f    // 266^-0.5
#define PHI_EPS     1e-4f
#define LN_EPS      1e-12f

// ---------------- scratch (device globals; no allocs) ----------------
__device__ float g_x   [NROWS*Dc];
__device__ float g_xn  [NROWS*Dc];
__device__ float g_q   [NROWS*Dc];
__device__ float g_k   [NROWS*Dc];
__device__ float g_v   [NROWS*Dc];
__device__ float g_attn[NROWS*Dc];
__device__ float g_hid [NROWS*FFc];
__device__ float g_qp  [(long)BHc*Sc*MP];
__device__ float g_kp  [(long)BHc*Sc*MP];
__device__ float g_diag [BHc*Sc];
__device__ float g_diagq[BHc*Sc];
__device__ float g_dinv[BHc*Sc];
__device__ float g_ctx [BHc*Mc*DHc];
__device__ float g_ksum[BHc*Mc];
__device__ float g_ctxp [8*BHc*Mc*DHc];
__device__ float g_ksump[8*BHc*Mc];
__device__ float g_alpha[NROWS];
__device__ float g_asum [Bc];
__device__ float g_poolp[32*Bc*Dc];
__device__ float g_projpad[MP*DHc];
__device__ float g_kmax;

// ---------------- helpers ----------------
__device__ __forceinline__ void atomicMaxFloat(float* addr, float val){
    if (val >= 0.f) atomicMax((int*)addr, __float_as_int(val));
    else            atomicMin((unsigned int*)addr, __float_as_uint(val));
}

// ---------------- LayerNorm kernels ----------------
__global__ __launch_bounds__(256)
void ln_embed_kernel(const float* __restrict__ emb, const float* __restrict__ pos,
                     const float* __restrict__ gam, const float* __restrict__ bet,
                     float* __restrict__ out){
    int row = blockIdx.x;
    int t   = threadIdx.x;
    float v = emb[row*Dc + t] + pos[(row & (Sc-1))*Dc + t];
    float s1 = v, s2 = v*v;
    __shared__ float sa[8], sb[8];
    #pragma unroll
    for (int o=16;o;o>>=1){ s1 += __shfl_xor_sync(0xffffffffu,s1,o); s2 += __shfl_xor_sync(0xffffffffu,s2,o); }
    if ((t&31)==0){ sa[t>>5]=s1; sb[t>>5]=s2; }
    __syncthreads();
    if (t==0){ float a=0,b=0; for(int i=0;i<8;i++){a+=sa[i]; b+=sb[i];} sa[0]=a; sb[0]=b; }
    __syncthreads();
    float mu  = sa[0]*(1.f/Dc);
    float var = sb[0]*(1.f/Dc) - mu*mu;
    out[row*Dc + t] = (v-mu)*rsqrtf(var+LN_EPS)*gam[t] + bet[t];
}

__global__ __launch_bounds__(256)
void ln_kernel(const float* __restrict__ in,
               const float* __restrict__ gam, const float* __restrict__ bet,
               float* __restrict__ out){
    int row = blockIdx.x;
    int t   = threadIdx.x;
    float v = in[row*Dc + t];
    float s1 = v, s2 = v*v;
    __shared__ float sa[8], sb[8];
    #pragma unroll
    for (int o=16;o;o>>=1){ s1 += __shfl_xor_sync(0xffffffffu,s1,o); s2 += __shfl_xor_sync(0xffffffffu,s2,o); }
    if ((t&31)==0){ sa[t>>5]=s1; sb[t>>5]=s2; }
    __syncthreads();
    if (t==0){ float a=0,b=0; for(int i=0;i<8;i++){a+=sa[i]; b+=sb[i];} sa[0]=a; sb[0]=b; }
    __syncthreads();
    float mu  = sa[0]*(1.f/Dc);
    float var = sb[0]*(1.f/Dc) - mu*mu;
    out[row*Dc + t] = (v-mu)*rsqrtf(var+LN_EPS)*gam[t] + bet[t];
}

// ---------------- tf32 wmma GEMM 128x128x32, reg-prefetch pipeline ----------------
// blockIdx.z selects (W,bias,C) among up to 3 sets (QKV fusion); res only for z==0.
__global__ __launch_bounds__(256)
void gemm_kernel(const float* __restrict__ A,
                 const float* __restrict__ W0, const float* __restrict__ b0,
                 const float* __restrict__ W1p, const float* __restrict__ b1p,
                 const float* __restrict__ W2p, const float* __restrict__ b2p,
                 const float* __restrict__ res,
                 float* __restrict__ C0, float* __restrict__ C1, float* __restrict__ C2,
                 int K, int N, int act){
    const float* W = W0; const float* bias = b0; float* C = C0;
    if (blockIdx.z == 1){ W = W1p; bias = b1p; C = C1; }
    else if (blockIdx.z == 2){ W = W2p; bias = b2p; C = C2; }

    __shared__ float smem[8832];
    float (*As)[36]  = (float(*)[36])smem;           // 128 x 36
    float (*Bs)[132] = (float(*)[132])(smem + 4608); // 32 x 132
    float (*Cs)[132] = (float(*)[132])smem;          // 64 x 132 (epilogue reuse)

    int bm = blockIdx.y * 128;
    int bn = blockIdx.x * 128;
    int tid = threadIdx.x;
    int wid = tid >> 5;
    int warp_m = wid >> 1;
    int warp_n = wid & 1;

    wmma::fragment<wmma::accumulator,16,16,8,float> acc[2][4];
    #pragma unroll
    for (int i=0;i<2;i++)
        #pragma unroll
        for (int j=0;j<4;j++) wmma::fill_fragment(acc[i][j], 0.f);

    float4 pa[4], pb[4];
    // prefetch slab 0
    #pragma unroll
    for (int i=0;i<4;i++){
        int lin = tid + i*256;
        int r = lin >> 3, k4 = (lin & 7)*4;
        pa[i] = *(const float4*)&A[(bm+r)*K + k4];
    }
    #pragma unroll
    for (int i=0;i<4;i++){
        int lin = tid + i*256;
        int kr = lin >> 5, c4 = (lin & 31)*4;
        pb[i] = *(const float4*)&W[kr*N + bn + c4];
    }

    for (int k0 = 0; k0 < K; k0 += 32){
        __syncthreads();   // previous compute done before smem overwrite
        #pragma unroll
        for (int i=0;i<4;i++){
            int lin = tid + i*256;
            int r = lin >> 3, k4 = (lin & 7)*4;
            *(float4*)&As[r][k4] = pa[i];
        }
        #pragma unroll
        for (int i=0;i<4;i++){
            int lin = tid + i*256;
            int kr = lin >> 5, c4 = (lin & 31)*4;
            *(float4*)&Bs[kr][c4] = pb[i];
        }
        __syncthreads();
        if (k0 + 32 < K){
            #pragma unroll
            for (int i=0;i<4;i++){
                int lin = tid + i*256;
                int r = lin >> 3, k4 = (lin & 7)*4;
                pa[i] = *(const float4*)&A[(bm+r)*K + k0 + 32 + k4];
            }
            #pragma unroll
            for (int i=0;i<4;i++){
                int lin = tid + i*256;
                int kr = lin >> 5, c4 = (lin & 31)*4;
                pb[i] = *(const float4*)&W[(k0+32+kr)*N + bn + c4];
            }
        }
        #pragma unroll
        for (int kk = 0; kk < 32; kk += 8){
            wmma::fragment<wmma::matrix_a,16,16,8,wmma::precision::tf32,wmma::row_major> af[2];
            wmma::fragment<wmma::matrix_b,16,16,8,wmma::precision::tf32,wmma::row_major> bf[4];
            #pragma unroll
            for (int i=0;i<2;i++){
                wmma::load_matrix_sync(af[i], &As[warp_m*32 + i*16][kk], 36);
                #pragma unroll
                for (int e=0;e<af[i].num_elements;e++) af[i].x[e] = wmma::__float_to_tf32(af[i].x[e]);
            }
            #pragma unroll
            for (int j=0;j<4;j++){
                wmma::load_matrix_sync(bf[j], &Bs[kk][warp_n*64 + j*16], 132);
                #pragma unroll
                for (int e=0;e<bf[j].num_elements;e++) bf[j].x[e] = wmma::__float_to_tf32(bf[j].x[e]);
            }
            #pragma unroll
            for (int i=0;i<2;i++)
                #pragma unroll
                for (int j=0;j<4;j++)
                    wmma::mma_sync(acc[i][j], af[i], bf[j], acc[i][j]);
        }
    }
    __syncthreads();
    // epilogue: two phases of 64 rows staged through smem
    #pragma unroll
    for (int phase = 0; phase < 2; phase++){
        if ((warp_m >> 1) == phase){
            int rbase = (warp_m & 1)*32;
            #pragma unroll
            for (int i=0;i<2;i++)
                #pragma unroll
                for (int j=0;j<4;j++)
                    wmma::store_matrix_sync(&Cs[rbase + i*16][warp_n*64 + j*16],
                                            acc[i][j], 132, wmma::mem_row_major);
        }
        __syncthreads();
        #pragma unroll
        for (int i=0;i<8;i++){
            int lin = tid + i*256;
            int r = lin >> 5, c4 = (lin & 31)*4;
            int rg = bm + phase*64 + r;
            float4 v4 = *(float4*)&Cs[r][c4];
            float vv[4] = {v4.x, v4.y, v4.z, v4.w};
            float rr[4] = {0.f,0.f,0.f,0.f};
            if (res){
                float4 r4 = *(const float4*)&res[rg*N + bn + c4];
                rr[0]=r4.x; rr[1]=r4.y; rr[2]=r4.z; rr[3]=r4.w;
            }
            float4 o4;
            float* ov = (float*)&o4;
            #pragma unroll
            for (int j=0;j<4;j++){
                int c = bn + c4 + j;
                float val = vv[j] + bias[c] + rr[j];
                if (act == 1){
                    float x = val;
                    val = 0.5f*x*(1.f + tanhf(0.7978845608028654f*(x + 0.044715f*x*x*x)));
                } else if (act == 2){
                    val = tanhf(val);
                }
                ov[j] = val;
            }
            *(float4*)&C[rg*N + bn + c4] = o4;
        }
        __syncthreads();
    }
}

// ---------------- proj padding: [Mc,64] -> [MP,64] zero-padded ----------------
__global__ __launch_bounds__(256)
void copy_proj_kernel(const float* __restrict__ proj){
    int i = blockIdx.x*256 + threadIdx.x;      // grid covers MP*DHc
    int m = i >> 6;
    g_projpad[i] = (m < Mc) ? proj[i] : 0.f;   // i = m*64+k, valid while m<Mc
}

// ---------------- phi matmul: dash = (x_head @ projpad^T)*DN, + diag ----------------
// Block: 64 s-rows of one (b,h), full MP=288 cols. 8 warps: 4(m) x 2(n).
__global__ __launch_bounds__(256)
void phi_mm_kernel(const float* __restrict__ in, float* __restrict__ dash,
                   float* __restrict__ diag){
    __shared__ float As[64][68];
    int b = blockIdx.z, h = blockIdx.y, s0 = blockIdx.x*64;
    int bh = b*Hc + h;
    int t = threadIdx.x;
    int wid = t >> 5;
    int wm = wid >> 1;          // 0..3 -> 16-row tile
    int wn = wid & 1;           // 0..1 -> 144-col half
    #pragma unroll
    for (int i=0;i<4;i++){
        int lin = t + i*256;
        int r = lin >> 4, k4 = (lin & 15)*4;
        *(float4*)&As[r][k4] = *(const float4*)&in[(b*Sc + s0 + r)*Dc + h*DHc + k4];
    }
    __syncthreads();
    if (t < 64){
        float s = 0.f;
        #pragma unroll
        for (int k=0;k<64;k++){ float x = As[t][k]; s += x*x; }
        diag[bh*Sc + s0 + t] = s*DIAG_SCALE;
    }
    wmma::fragment<wmma::accumulator,16,16,8,float> acc[9];
    #pragma unroll
    for (int j=0;j<9;j++) wmma::fill_fragment(acc[j], 0.f);
    #pragma unroll
    for (int kk = 0; kk < 64; kk += 8){
        wmma::fragment<wmma::matrix_a,16,16,8,wmma::precision::tf32,wmma::row_major> af;
        wmma::load_matrix_sync(af, &As[wm*16][kk], 68);
        #pragma unroll
        for (int e=0;e<af.num_elements;e++) af.x[e] = wmma::__float_to_tf32(af.x[e]);
        #pragma unroll
        for (int j=0;j<9;j++){
            wmma::fragment<wmma::matrix_b,16,16,8,wmma::precision::tf32,wmma::col_major> bf;
            wmma::load_matrix_sync(bf, &g_projpad[(wn*144 + j*16)*DHc + kk], DHc);
            #pragma unroll
            for (int e=0;e<bf.num_elements;e++) bf.x[e] = wmma::__float_to_tf32(bf.x[e]);
            wmma::mma_sync(acc[j], af, bf, acc[j]);
        }
    }
    long rowbase = ((long)bh*Sc + s0 + wm*16)*MP;
    #pragma unroll
    for (int j=0;j<9;j++){
        #pragma unroll
        for (int e=0;e<acc[j].num_elements;e++) acc[j].x[e] *= DN_CONST;
        wmma::store_matrix_sync(&dash[rowbase + wn*144 + j*16], acc[j], MP, wmma::mem_row_major);
    }
}

// ---------------- q epilogue: per-row max, exp ----------------
__global__ __launch_bounds__(256)
void phi_q_ep_kernel(float* __restrict__ qp, const float* __restrict__ diag){
    int row  = blockIdx.x*8 + (threadIdx.x>>5);
    int lane = threadIdx.x & 31;
    long base = (long)row*MP;
    float v[9]; float mx = -1e30f;
    #pragma unroll
    for (int j=0;j<9;j++){
        int m = lane + 32*j;
        v[j] = (m < Mc) ? qp[base + m] : -1e30f;
        mx = fmaxf(mx, v[j]);
    }
    #pragma unroll
    for (int o=16;o;o>>=1) mx = fmaxf(mx, __shfl_xor_sync(0xffffffffu, mx, o));
    float dg = diag[row];
    #pragma unroll
    for (int j=0;j<9;j++){
        int m = lane + 32*j;
        if (m < Mc) qp[base + m] = RATIO_CONST*(expf(v[j] - dg - mx) + PHI_EPS);
    }
}

__global__ void reset_kmax_kernel(){ g_kmax = __int_as_float(0xff800000); }

// ---------------- k global max over dash (masked) ----------------
__global__ __launch_bounds__(256)
void kmax_kernel(const float* __restrict__ dash){
    __shared__ float red[8];
    float mx = -1e30f;
    long total = (long)BHc*Sc*MP;
    for (long i = (long)blockIdx.x*256 + threadIdx.x; i < total; i += (long)gridDim.x*256){
        int m = (int)(i % MP);
        if (m < Mc) mx = fmaxf(mx, dash[i]);
    }
    #pragma unroll
    for (int o=16;o;o>>=1) mx = fmaxf(mx, __shfl_xor_sync(0xffffffffu, mx, o));
    if ((threadIdx.x & 31) == 0) red[threadIdx.x>>5] = mx;
    __syncthreads();
    if (threadIdx.x == 0){
        float m2 = -1e30f;
        for (int i=0;i<8;i++) m2 = fmaxf(m2, red[i]);
        atomicMaxFloat(&g_kmax, m2);
    }
}

// ---------------- k epilogue: exp with global stabilizer (padded cols harmless) ----------------
__global__ __launch_bounds__(256)
void phi_k2_kernel(float* __restrict__ kp, const float* __restrict__ diag){
    long i = (long)blockIdx.x*256 + threadIdx.x;
    int row = (int)(i / MP);
    kp[i] = RATIO_CONST*(expf(kp[i] - diag[row] - g_kmax) + PHI_EPS);
}

// ---------------- ctx = kp^T @ v (plus ksum), 2-stage over 8 s-splits ----------------
__global__ __launch_bounds__(256)
void ctx_part_kernel(const float* __restrict__ kp, const float* __restrict__ v,
                     float* __restrict__ ctxp, float* __restrict__ ksump){
    __shared__ float ks_s[32][68];
    __shared__ float vs[32][64];
    int mt = blockIdx.x, bh = blockIdx.y, sp = blockIdx.z;
    int b = bh >> 2, h = bh & 3;
    int t = threadIdx.x;
    int tr = t >> 4, tc = t & 15;
    float acc[4][4] = {};
    float ks[4] = {};
    int sbeg = sp*(Sc/8);
    for (int s0 = sbeg; s0 < sbeg + Sc/8; s0 += 32){
        #pragma unroll
        for (int it = 0; it < 8; it++){
            int idx = t + it*256;
            int ss = idx >> 6, ml = idx & 63;
            int m = mt*64 + ml;
            ks_s[ss][ml] = (m < Mc) ? kp[((long)bh*Sc + s0 + ss)*MP + m] : 0.f;
        }
        #pragma unroll
        for (int it = 0; it < 8; it++){
            int idx = t + it*256;
            int ss = idx >> 6, e = idx & 63;
            vs[ss][e] = v[(b*Sc + s0 + ss)*Dc + h*DHc + e];
        }
        __syncthreads();
        #pragma unroll
        for (int ss = 0; ss < 32; ss++){
            float a[4];
            #pragma unroll
            for (int i = 0; i < 4; i++) a[i] = ks_s[ss][tr*4 + i];
            float4 c4 = *(const float4*)(&vs[ss][tc*4]);
            float c[4] = {c4.x, c4.y, c4.z, c4.w};
            #pragma unroll
            for (int i = 0; i < 4; i++){
                #pragma unroll
                for (int j = 0; j < 4; j++) acc[i][j] += a[i]*c[j];
            }
            if (tc == 0){
                #pragma unroll
                for (int i = 0; i < 4; i++) ks[i] += a[i];
            }
        }
        __syncthreads();
    }
    #pragma unroll
    for (int i = 0; i < 4; i++){
        int m = mt*64 + tr*4 + i;
        if (m < Mc){
            float* cp = ctxp + (((long)sp*BHc + bh)*Mc + m)*DHc + tc*4;
            float4 o4 = make_float4(acc[i][0], acc[i][1], acc[i][2], acc[i][3]);
            *(float4*)cp = o4;
            if (tc == 0) ksump[((long)sp*BHc + bh)*Mc + m] = ks[i];
        }
    }
}

__global__ __launch_bounds__(256)
void ctx_reduce_kernel(const float* __restrict__ ctxp, const float* __restrict__ ksump,
                       float* __restrict__ ctx, float* __restrict__ ksum){
    int i = blockIdx.x*256 + threadIdx.x;
    if (i < BHc*Mc*DHc){
        float s = 0.f;
        #pragma unroll
        for (int sp = 0; sp < 8; sp++) s += ctxp[(long)sp*BHc*Mc*DHc + i];
        ctx[i] = s;
    }
    if (i < BHc*Mc){
        float s = 0.f;
        #pragma unroll
        for (int sp = 0; sp < 8; sp++) s += ksump[sp*BHc*Mc + i];
        ksum[i] = s;
    }
}

// ---------------- d_inv ----------------
__global__ __launch_bounds__(256)
void dinv_kernel(const float* __restrict__ qp, const float* __restrict__ ksum,
                 float* __restrict__ dinv){
    int row  = blockIdx.x*8 + (threadIdx.x>>5);
    int lane = threadIdx.x & 31;
    int bh   = row / Sc;
    const float* qr = qp + (long)row*MP;
    const float* kr = ksum + bh*Mc;
    float a = 0.f;
    for (int m=lane;m<Mc;m+=32) a += qr[m]*kr[m];
    #pragma unroll
    for (int o=16;o;o>>=1) a += __shfl_xor_sync(0xffffffffu,a,o);
    if (lane == 0) dinv[row] = 1.f/a;
}

// ---------------- attention out: (qp @ ctx) * dinv ----------------
__global__ __launch_bounds__(256)
void attn_out_kernel(const float* __restrict__ qp, const float* __restrict__ ctx,
                     const float* __restrict__ dinv, float* __restrict__ attn){
    __shared__ float qs_t[32][68];
    __shared__ float cs[32][64];
    int bh = blockIdx.y;
    int b = bh >> 2, h = bh & 3;
    int s0 = blockIdx.x*64;
    int t = threadIdx.x;
    int tr = t >> 4, tc = t & 15;
    float acc[4][4] = {};
    for (int m0 = 0; m0 < MP; m0 += 32){
        #pragma unroll
        for (int it = 0; it < 8; it++){
            int idx = t + it*256;
            int s = idx >> 5, mm = idx & 31;
            int m = m0 + mm;
            qs_t[mm][s] = (m < Mc) ? qp[((long)bh*Sc + s0 + s)*MP + m] : 0.f;
        }
        #pragma unroll
        for (int it = 0; it < 8; it++){
            int idx = t + it*256;
            int mm = idx >> 6, e = idx & 63;
            int m = m0 + mm;
            cs[mm][e] = (m < Mc) ? ctx[((long)bh*Mc + m)*DHc + e] : 0.f;
        }
        __syncthreads();
        #pragma unroll
        for (int mm = 0; mm < 32; mm++){
            float a[4];
            #pragma unroll
            for (int i = 0; i < 4; i++) a[i] = qs_t[mm][tr*4 + i];
            float4 c4 = *(const float4*)(&cs[mm][tc*4]);
            float c[4] = {c4.x, c4.y, c4.z, c4.w};
            #pragma unroll
            for (int i = 0; i < 4; i++)
                #pragma unroll
                for (int j = 0; j < 4; j++) acc[i][j] += a[i]*c[j];
        }
        __syncthreads();
    }
    #pragma unroll
    for (int i = 0; i < 4; i++){
        int s = s0 + tr*4 + i;
        float di = dinv[bh*Sc + s];
        float4 o4 = make_float4(acc[i][0]*di, acc[i][1]*di, acc[i][2]*di, acc[i][3]*di);
        *(float4*)(&attn[(b*Sc + s)*Dc + h*DHc + tc*4]) = o4;
    }
}

// ---------------- pooling ----------------
__global__ __launch_bounds__(256)
void alpha_kernel(const float* __restrict__ e, const float* __restrict__ p2w,
                  const float* __restrict__ p2b, const float* __restrict__ mask,
                  float* __restrict__ alpha){
    int row  = blockIdx.x*8 + (threadIdx.x>>5);
    int lane = threadIdx.x & 31;
    const float* er = e + row*Dc;
    float a = 0.f;
    for (int d=lane; d<Dc; d+=32) a += er[d]*p2w[d];
    #pragma unroll
    for (int o=16;o;o>>=1) a += __shfl_xor_sync(0xffffffffu,a,o);
    if (lane == 0) alpha[row] = expf(a + p2b[0])*mask[row];
}

__global__ __launch_bounds__(256)
void asum_kernel(const float* __restrict__ alpha, float* __restrict__ asum){
    int b = blockIdx.x, t = threadIdx.x;
    float s = 0.f;
    for (int i=t;i<Sc;i+=256) s += alpha[b*Sc + i];
    __shared__ float sa[8];
    #pragma unroll
    for (int o=16;o;o>>=1) s += __shfl_xor_sync(0xffffffffu,s,o);
    if ((t&31)==0) sa[t>>5] = s;
    __syncthreads();
    if (t == 0){ float a=0; for (int i=0;i<8;i++) a += sa[i]; asum[b] = a + 1e-8f; }
}

__global__ __launch_bounds__(256)
void pool_part_kernel(const float* __restrict__ x, const float* __restrict__ alpha,
                      float* __restrict__ pp){
    int b = blockIdx.y, c = blockIdx.x, d = threadIdx.x;
    float acc = 0.f;
    int s0 = c*(Sc/32);
    for (int s=s0;s<s0+Sc/32;s++) acc += x[(b*Sc + s)*Dc + d]*alpha[b*Sc + s];
    pp[(c*Bc + b)*Dc + d] = acc;
}

__global__ __launch_bounds__(256)
void pool_reduce_kernel(const float* __restrict__ pp, const float* __restrict__ asum,
                        float* __restrict__ out){
    int i = blockIdx.x*256 + threadIdx.x;
    if (i < Bc*Dc){
        int b = i / Dc, d = i - b*Dc;
        float s = 0.f;
        #pragma unroll
        for (int c=0;c<32;c++) s += pp[(c*Bc + b)*Dc + d];
        out[i] = s / asum[b];
    }
}

// ---------------- host launcher ----------------
extern "C" void kernel_launch(void* const* d_in, const int* in_sizes, int n_in,
                              void* d_out, int out_size){
    const float* input_embs = (const float*)d_in[0];
    const float* mask   = (const float*)d_in[1];
    const float* pos    = (const float*)d_in[2];
    const float* ln_g   = (const float*)d_in[3];
    const float* ln_b   = (const float*)d_in[4];
    const float* proj   = (const float*)d_in[5];
    const float* Wq     = (const float*)d_in[6];
    const float* bq     = (const float*)d_in[7];
    const float* Wk     = (const float*)d_in[8];
    const float* bk     = (const float*)d_in[9];
    const float* Wv     = (const float*)d_in[10];
    const float* bv     = (const float*)d_in[11];
    const float* Wo     = (const float*)d_in[12];
    const float* bo     = (const float*)d_in[13];
    const float* ln1_g  = (const float*)d_in[14];
    const float* ln1_b  = (const float*)d_in[15];
    const float* W1     = (const float*)d_in[16];
    const float* b1     = (const float*)d_in[17];
    const float* W2     = (const float*)d_in[18];
    const float* b2     = (const float*)d_in[19];
    const float* ln2_g  = (const float*)d_in[20];
    const float* ln2_b  = (const float*)d_in[21];
    const float* p1w    = (const float*)d_in[22];
    const float* p1b    = (const float*)d_in[23];
    const float* p2w    = (const float*)d_in[24];
    const float* p2b    = (const float*)d_in[25];
    float* out = (float*)d_out;

    void* p;
    float *X,*XN,*Q,*Kb,*V,*AT,*HID,*QP,*KP,*DIAG,*DIAGQ,*DINV,*CTX,*KSUM,*CTXP,*KSUMP,*ALPHA,*ASUM,*PP;
    cudaGetSymbolAddress(&p, g_x);     X     = (float*)p;
    cudaGetSymbolAddress(&p, g_xn);    XN    = (float*)p;
    cudaGetSymbolAddress(&p, g_q);     Q     = (float*)p;
    cudaGetSymbolAddress(&p, g_k);     Kb    = (float*)p;
    cudaGetSymbolAddress(&p, g_v);     V     = (float*)p;
    cudaGetSymbolAddress(&p, g_attn);  AT    = (float*)p;
    cudaGetSymbolAddress(&p, g_hid);   HID   = (float*)p;
    cudaGetSymbolAddress(&p, g_qp);    QP    = (float*)p;
    cudaGetSymbolAddress(&p, g_kp);    KP    = (float*)p;
    cudaGetSymbolAddress(&p, g_diag);  DIAG  = (float*)p;
    cudaGetSymbolAddress(&p, g_diagq); DIAGQ = (float*)p;
    cudaGetSymbolAddress(&p, g_dinv);  DINV  = (float*)p;
    cudaGetSymbolAddress(&p, g_ctx);   CTX   = (float*)p;
    cudaGetSymbolAddress(&p, g_ksum);  KSUM  = (float*)p;
    cudaGetSymbolAddress(&p, g_ctxp);  CTXP  = (float*)p;
    cudaGetSymbolAddress(&p, g_ksump); KSUMP = (float*)p;
    cudaGetSymbolAddress(&p, g_alpha); ALPHA = (float*)p;
    cudaGetSymbolAddress(&p, g_asum);  ASUM  = (float*)p;
    cudaGetSymbolAddress(&p, g_poolp); PP    = (float*)p;

    // x = LN(input + pos)
    ln_embed_kernel<<<NROWS, 256>>>(input_embs, pos, ln_g, ln_b, X);

    for (int l = 0; l < Lc; l++){
        const float* prj = proj + l*Mc*DHc;
        // ln1
        ln_kernel<<<NROWS, 256>>>(X, ln1_g + l*Dc, ln1_b + l*Dc, XN);
        // fused QKV (grid.z = 3)
        gemm_kernel<<<dim3(Dc/128, NROWS/128, 3), 256>>>(XN,
            Wq + l*Dc*Dc, bq + l*Dc, Wk + l*Dc*Dc, bk + l*Dc, Wv + l*Dc*Dc, bv + l*Dc,
            nullptr, Q, Kb, V, Dc, Dc, 0);
        // phi features (wmma) + stabilizer epilogues
        copy_proj_kernel<<<(MP*DHc)/256, 256>>>(prj);
        phi_mm_kernel<<<dim3(Sc/64, Hc, Bc), 256>>>(Q,  QP, DIAGQ);
        phi_mm_kernel<<<dim3(Sc/64, Hc, Bc), 256>>>(Kb, KP, DIAG);
        phi_q_ep_kernel<<<(BHc*Sc)/8, 256>>>(QP, DIAGQ);
        reset_kmax_kernel<<<1,1>>>();
        kmax_kernel<<<2048, 256>>>(KP);
        phi_k2_kernel<<<(long)(BHc*Sc*MP)/256, 256>>>(KP, DIAG);
        // ctx + ksum
        ctx_part_kernel<<<dim3((Mc+63)/64, BHc, 8), 256>>>(KP, V, CTXP, KSUMP);
        ctx_reduce_kernel<<<(BHc*Mc*DHc + 255)/256, 256>>>(CTXP, KSUMP, CTX, KSUM);
        // normalizer + output
        dinv_kernel<<<(BHc*Sc)/8, 256>>>(QP, KSUM, DINV);
        attn_out_kernel<<<dim3(Sc/64, BHc), 256>>>(QP, CTX, DINV, AT);
        // x += attn @ Wo + bo
        gemm_kernel<<<dim3(Dc/128, NROWS/128), 256>>>(AT,
            Wo + l*Dc*Dc, bo + l*Dc, nullptr, nullptr, nullptr, nullptr,
            X, X, nullptr, nullptr, Dc, Dc, 0);
        // FFN
        ln_kernel<<<NROWS, 256>>>(X, ln2_g + l*Dc, ln2_b + l*Dc, XN);
        gemm_kernel<<<dim3(FFc/128, NROWS/128), 256>>>(XN,
            W1 + l*Dc*FFc, b1 + l*FFc, nullptr, nullptr, nullptr, nullptr,
            nullptr, HID, nullptr, nullptr, Dc, FFc, 1);
        gemm_kernel<<<dim3(Dc/128, NROWS/128), 256>>>(HID,
            W2 + l*FFc*Dc, b2 + l*Dc, nullptr, nullptr, nullptr, nullptr,
            X, X, nullptr, nullptr, FFc, Dc, 0);
    }

    // attention pooling
    gemm_kernel<<<dim3(Dc/128, NROWS/128), 256>>>(X,
        p1w, p1b, nullptr, nullptr, nullptr, nullptr,
        nullptr, XN, nullptr, nullptr, Dc, Dc, 2);
    alpha_kernel<<<NROWS/8, 256>>>(XN, p2w, p2b, mask, ALPHA);
    asum_kernel<<<Bc, 256>>>(ALPHA, ASUM);
    pool_part_kernel<<<dim3(32, Bc), 256>>>(X, ALPHA, PP);
    pool_reduce_kernel<<<(Bc*Dc + 255)/256, 256>>>(PP, ASUM, out);
}